// round 4
// baseline (speedup 1.0000x reference)
#include <cuda_runtime.h>
#include <cstdint>

#define T_STEPS 512
#define BATCH   64
#define IDIM    256
#define HDIM    512
#define NCTA    128
#define NTHR    256
#define NTHR2   512
#define JCOL    4
#define GR      16            // gate rows per CTA
#define GSTR    68            // gate-exchange row stride (16B-aligned, +4 banks)

typedef unsigned long long ull;

// ---- persistent device scratch (static: no runtime allocation) ----
__device__ float g_xw[(size_t)T_STEPS * NCTA * GR * BATCH];   // [t][cta][row][b], bias folded in
__device__ float g_hbuf[2][BATCH * HDIM];
__device__ unsigned int g_bar_count;
__device__ unsigned int g_bar_epoch;

__device__ __forceinline__ ull fma2(ull a, ull b, ull c) {
    ull d;
    asm("fma.rn.f32x2 %0, %1, %2, %3;" : "=l"(d) : "l"(a), "l"(b), "l"(c));
    return d;
}
__device__ __forceinline__ float hsum2(ull a) {
    return __uint_as_float((unsigned)(a & 0xffffffffu)) +
           __uint_as_float((unsigned)(a >> 32));
}
__device__ __forceinline__ float sigmoidf_(float v) {
    return __fdividef(1.0f, 1.0f + __expf(-v));
}
__device__ __forceinline__ void cpasync16(uint32_t dst, const void* src) {
    asm volatile("cp.async.cg.shared.global [%0], [%1], 16;" :: "r"(dst), "l"(src));
}
#define CP_COMMIT() asm volatile("cp.async.commit_group;" ::: "memory")
#define CP_WAIT(n)  asm volatile("cp.async.wait_group %0;" :: "n"(n) : "memory")

// 16-wide fma2 update: one 4-float k-slab of w0/w1 against 4 activation rows
#define MACBLK(kkv)                                                        \
    {                                                                      \
        ulonglong2 w0v = *(const ulonglong2*)(w0 + (kkv));                 \
        ulonglong2 w1v = *(const ulonglong2*)(w1 + (kkv));                 \
        ulonglong2 av;                                                     \
        av = *(const ulonglong2*)(a0p + (kkv));                            \
        A0  = fma2(w0v.x, av.x, A0);  A1  = fma2(w0v.y, av.y, A1);         \
        A2  = fma2(w1v.x, av.x, A2);  A3  = fma2(w1v.y, av.y, A3);         \
        av = *(const ulonglong2*)(a1p + (kkv));                            \
        A4  = fma2(w0v.x, av.x, A4);  A5  = fma2(w0v.y, av.y, A5);         \
        A6  = fma2(w1v.x, av.x, A6);  A7  = fma2(w1v.y, av.y, A7);         \
        av = *(const ulonglong2*)(a2p + (kkv));                            \
        A8  = fma2(w0v.x, av.x, A8);  A9  = fma2(w0v.y, av.y, A9);         \
        A10 = fma2(w1v.x, av.x, A10); A11 = fma2(w1v.y, av.y, A11);        \
        av = *(const ulonglong2*)(a3p + (kkv));                            \
        A12 = fma2(w0v.x, av.x, A12); A13 = fma2(w0v.y, av.y, A13);        \
        A14 = fma2(w1v.x, av.x, A14); A15 = fma2(w1v.y, av.y, A15);        \
    }

// ============================================================================
// Phase 1: xw[t] = x_t @ Wall^T + (bW + bU), fully parallel.
// ============================================================================
#define P1_TT   16
#define P1_WXS  260
#define P1_CKP  132
#define P1_OFF_WX   0
#define P1_OFF_ASH  (P1_OFF_WX + GR * P1_WXS)
#define P1_OFF_GSM  (P1_OFF_ASH + 2 * BATCH * P1_CKP)
#define P1_OFF_BS   (P1_OFF_GSM + 2 * GR * GSTR)
#define P1_FLOATS   (P1_OFF_BS + GR)

__global__ void __launch_bounds__(NTHR, 2)
lstm_xw_kernel(const float* __restrict__ x,
               const float* __restrict__ Wf, const float* __restrict__ bWf,
               const float* __restrict__ Wi, const float* __restrict__ bWi,
               const float* __restrict__ Wo, const float* __restrict__ bWo,
               const float* __restrict__ Wc, const float* __restrict__ bWc,
               const float* __restrict__ bUf, const float* __restrict__ bUi,
               const float* __restrict__ bUo, const float* __restrict__ bUc)
{
    extern __shared__ float sm[];
    float* Wx  = sm + P1_OFF_WX;
    float* ash = sm + P1_OFF_ASH;
    float* gsm = sm + P1_OFF_GSM;
    float* bsm = sm + P1_OFF_BS;

    const int tid = threadIdx.x;
    const int kh  = tid >> 7;
    const int tl  = tid & 127;
    const int cg  = tl & 7;
    const int bg  = tl >> 3;
    const int jg  = blockIdx.x;
    const int j0  = jg * JCOL;
    const int t0  = blockIdx.y * P1_TT;

    {
        const float* Wg[4]  = {Wf, Wi, Wo, Wc};
        const float* bWg[4] = {bWf, bWi, bWo, bWc};
        const float* bUg[4] = {bUf, bUi, bUo, bUc};
        for (int idx = tid; idx < GR * IDIM; idx += NTHR) {
            int row = idx >> 8, k = idx & (IDIM - 1);
            int gate = row >> 2, j = row & 3;
            Wx[row * P1_WXS + k] = Wg[gate][(j0 + j) * IDIM + k];
        }
        if (tid < GR) {
            int gate = tid >> 2, j = tid & 3;
            bsm[tid] = bWg[gate][j0 + j] + bUg[gate][j0 + j];
        }
    }
    __syncthreads();

    const float* w0b = Wx + cg * P1_WXS + kh * 64;
    const float* w1b = Wx + (cg + 8) * P1_WXS + kh * 64;

    for (int tt = 0; tt < P1_TT; ++tt) {
        const int t = t0 + tt;
        const float* xt = x + (size_t)t * BATCH * IDIM;

        #pragma unroll
        for (int r = 0; r < 8; ++r) {
            int idx = tid + r * NTHR;
            int b = idx >> 5, q = idx & 31;
            float4 v = __ldg(reinterpret_cast<const float4*>(xt + b * IDIM + q * 4));
            *reinterpret_cast<float4*>(ash + b * P1_CKP + q * 4) = v;
        }
        __syncthreads();

        ull A0=0,A1=0,A2=0,A3=0,A4=0,A5=0,A6=0,A7=0;
        ull A8=0,A9=0,A10=0,A11=0,A12=0,A13=0,A14=0,A15=0;

        #pragma unroll
        for (int r = 0; r < 8; ++r) {
            int idx = tid + r * NTHR;
            int b = idx >> 5, q = idx & 31;
            float4 v = __ldg(reinterpret_cast<const float4*>(xt + b * IDIM + 128 + q * 4));
            *reinterpret_cast<float4*>(ash + BATCH * P1_CKP + b * P1_CKP + q * 4) = v;
        }
        {
            const float* abase = ash + kh * 64;
            const float* a0p = abase + (bg * 4 + 0) * P1_CKP;
            const float* a1p = abase + (bg * 4 + 1) * P1_CKP;
            const float* a2p = abase + (bg * 4 + 2) * P1_CKP;
            const float* a3p = abase + (bg * 4 + 3) * P1_CKP;
            const float* w0 = w0b;
            const float* w1 = w1b;
            #pragma unroll
            for (int kk = 0; kk < 64; kk += 4) MACBLK(kk)
        }
        __syncthreads();
        {
            const float* abase = ash + BATCH * P1_CKP + kh * 64;
            const float* a0p = abase + (bg * 4 + 0) * P1_CKP;
            const float* a1p = abase + (bg * 4 + 1) * P1_CKP;
            const float* a2p = abase + (bg * 4 + 2) * P1_CKP;
            const float* a3p = abase + (bg * 4 + 3) * P1_CKP;
            const float* w0 = w0b + 128;
            const float* w1 = w1b + 128;
            #pragma unroll
            for (int kk = 0; kk < 64; kk += 4) MACBLK(kk)
        }
        {
            float* g0 = gsm + kh * GR * GSTR + cg * GSTR + bg * 4;
            float* g1 = gsm + kh * GR * GSTR + (cg + 8) * GSTR + bg * 4;
            g0[0] = hsum2(A0)  + hsum2(A1);
            g1[0] = hsum2(A2)  + hsum2(A3);
            g0[1] = hsum2(A4)  + hsum2(A5);
            g1[1] = hsum2(A6)  + hsum2(A7);
            g0[2] = hsum2(A8)  + hsum2(A9);
            g1[2] = hsum2(A10) + hsum2(A11);
            g0[3] = hsum2(A12) + hsum2(A13);
            g1[3] = hsum2(A14) + hsum2(A15);
        }
        __syncthreads();
        {
            int row = tid >> 4;
            int b4  = (tid & 15) * 4;
            float4 p0 = *reinterpret_cast<float4*>(gsm + row * GSTR + b4);
            float4 p1 = *reinterpret_cast<float4*>(gsm + GR * GSTR + row * GSTR + b4);
            float bb = bsm[row];
            float4 o;
            o.x = p0.x + p1.x + bb;
            o.y = p0.y + p1.y + bb;
            o.z = p0.z + p1.z + bb;
            o.w = p0.w + p1.w + bb;
            *reinterpret_cast<float4*>(g_xw + (((size_t)t * NCTA + jg) * GR + row) * BATCH + b4) = o;
        }
        __syncthreads();
    }
}

// ============================================================================
// Phase 2: persistent recurrence, 512 threads, cp.async pipelined staging.
// K split 4 ways (kq): thread covers K in {kq*64..+64} of each 256-chunk.
// ============================================================================
#define P2_WHS  516           // U row stride (K=512 + pad)
#define P2_CKP  260           // act row stride (chunk K=256 + pad)
#define P2_OFF_WH   0
#define P2_OFF_ASH  (P2_OFF_WH + GR * P2_WHS)            // 8256
#define P2_OFF_GSM  (P2_OFF_ASH + 2 * BATCH * P2_CKP)    // +33280
#define P2_OFF_XW   (P2_OFF_GSM + 4 * GR * GSTR)         // +4352
#define P2_OFF_CSM  (P2_OFF_XW + GR * GSTR)              // +1088
#define P2_OFF_EB   (P2_OFF_CSM + 256)                   // +256
#define P2_FLOATS   (P2_OFF_EB + 4)

__global__ void __launch_bounds__(NTHR2, 1)
lstm_recur_kernel(const float* __restrict__ Uf, const float* __restrict__ Ui,
                  const float* __restrict__ Uo, const float* __restrict__ Uc,
                  float* __restrict__ out)
{
    extern __shared__ float sm[];
    float* Wh   = sm + P2_OFF_WH;
    float* ash  = sm + P2_OFF_ASH;
    float* gsm  = sm + P2_OFF_GSM;
    float* xwsm = sm + P2_OFF_XW;
    float* csm  = sm + P2_OFF_CSM;
    unsigned* ebase = (unsigned*)(sm + P2_OFF_EB);

    const int tid = threadIdx.x;
    const int kq  = tid >> 7;            // K-quarter 0..3 (64-wide per 256-chunk)
    const int tl  = tid & 127;
    const int cg  = tl & 7;
    const int bg  = tl >> 3;
    const int j0  = blockIdx.x * JCOL;

    const uint32_t sm_u32 = (uint32_t)__cvta_generic_to_shared(sm);
    const uint32_t ash_u32  = sm_u32 + P2_OFF_ASH * 4;
    const uint32_t xwsm_u32 = sm_u32 + P2_OFF_XW * 4;

    {
        const float* Ug[4] = {Uf, Ui, Uo, Uc};
        for (int idx = tid; idx < GR * HDIM; idx += NTHR2) {
            int row = idx >> 9, k = idx & (HDIM - 1);
            int gate = row >> 2, j = row & 3;
            Wh[row * P2_WHS + k] = Ug[gate][(j0 + j) * HDIM + k];
        }
        if (tid < 256) csm[tid] = 0.0f;
        if (tid == 0) *ebase = *(volatile unsigned*)&g_bar_epoch;
    }
    __syncthreads();
    const unsigned base_epoch = *ebase;

    float* hseq = out;
    float* hfin = out + (size_t)T_STEPS * BATCH * HDIM;
    float* cfin = hfin + BATCH * HDIM;

    const float* w0b = Wh + cg * P2_WHS + kq * 64;
    const float* w1b = Wh + (cg + 8) * P2_WHS + kq * 64;
    const float* xwblk0 = g_xw + (size_t)blockIdx.x * GR * BATCH;

    // staging indices: idx covers 64 rows x 64 float4s per chunk
    const int st_b = tid >> 3;           // with r*NTHR2 offsets below
    (void)st_b;

    for (int t = 0; t < T_STEPS; ++t) {
        const float* xwsrc = xwblk0 + (size_t)t * NCTA * GR * BATCH;

        if (t > 0) {
            const float* hprev = g_hbuf[t & 1];

            // group A: chunk0 (K 0:256) + xw block
            #pragma unroll
            for (int r = 0; r < 8; ++r) {
                int idx = tid + r * NTHR2;
                int b = idx >> 6, q = idx & 63;
                cpasync16(ash_u32 + (b * P2_CKP + q * 4) * 4,
                          hprev + b * HDIM + q * 4);
            }
            if (tid < 256) {
                int row = tid >> 4;
                int b4  = (tid & 15) * 4;
                cpasync16(xwsm_u32 + (row * GSTR + b4) * 4,
                          xwsrc + row * BATCH + b4);
            }
            CP_COMMIT();
            // group B: chunk1 (K 256:512)
            #pragma unroll
            for (int r = 0; r < 8; ++r) {
                int idx = tid + r * NTHR2;
                int b = idx >> 6, q = idx & 63;
                cpasync16(ash_u32 + (BATCH * P2_CKP + b * P2_CKP + q * 4) * 4,
                          hprev + b * HDIM + 256 + q * 4);
            }
            CP_COMMIT();

            CP_WAIT(1);                 // chunk0 + xw landed (own copies)
            __syncthreads();            // ... and everyone else's

            ull A0=0,A1=0,A2=0,A3=0,A4=0,A5=0,A6=0,A7=0;
            ull A8=0,A9=0,A10=0,A11=0,A12=0,A13=0,A14=0,A15=0;

            // compute chunk0 while chunk1 streams in
            {
                const float* abase = ash + kq * 64;
                const float* a0p = abase + (bg * 4 + 0) * P2_CKP;
                const float* a1p = abase + (bg * 4 + 1) * P2_CKP;
                const float* a2p = abase + (bg * 4 + 2) * P2_CKP;
                const float* a3p = abase + (bg * 4 + 3) * P2_CKP;
                const float* w0 = w0b;
                const float* w1 = w1b;
                #pragma unroll
                for (int kk = 0; kk < 64; kk += 4) MACBLK(kk)
            }
            CP_WAIT(0);
            __syncthreads();
            // compute chunk1
            {
                const float* abase = ash + BATCH * P2_CKP + kq * 64;
                const float* a0p = abase + (bg * 4 + 0) * P2_CKP;
                const float* a1p = abase + (bg * 4 + 1) * P2_CKP;
                const float* a2p = abase + (bg * 4 + 2) * P2_CKP;
                const float* a3p = abase + (bg * 4 + 3) * P2_CKP;
                const float* w0 = w0b + 256;
                const float* w1 = w1b + 256;
                #pragma unroll
                for (int kk = 0; kk < 64; kk += 4) MACBLK(kk)
            }
            // write per-quarter partial gate sums
            {
                float* g0 = gsm + kq * GR * GSTR + cg * GSTR + bg * 4;
                float* g1 = gsm + kq * GR * GSTR + (cg + 8) * GSTR + bg * 4;
                g0[0] = hsum2(A0)  + hsum2(A1);
                g1[0] = hsum2(A2)  + hsum2(A3);
                g0[1] = hsum2(A4)  + hsum2(A5);
                g1[1] = hsum2(A6)  + hsum2(A7);
                g0[2] = hsum2(A8)  + hsum2(A9);
                g1[2] = hsum2(A10) + hsum2(A11);
                g0[3] = hsum2(A12) + hsum2(A13);
                g1[3] = hsum2(A14) + hsum2(A15);
            }
            __syncthreads();
        } else {
            if (tid < 256) {
                int row = tid >> 4;
                int b4  = (tid & 15) * 4;
                float4 v = __ldg(reinterpret_cast<const float4*>(xwsrc + row * BATCH + b4));
                *reinterpret_cast<float4*>(xwsm + row * GSTR + b4) = v;
            }
            __syncthreads();
        }

        // elementwise LSTM update (tid < 256: one (j,b) element each)
        float* hnext = g_hbuf[(t + 1) & 1];
        if (tid < 256) {
            int j = tid & 3;
            int b = tid >> 2;
            float gf = xwsm[(0*JCOL+j)*GSTR + b];
            float gi = xwsm[(1*JCOL+j)*GSTR + b];
            float go = xwsm[(2*JCOL+j)*GSTR + b];
            float gc = xwsm[(3*JCOL+j)*GSTR + b];
            if (t > 0) {
                #pragma unroll
                for (int q = 0; q < 4; ++q) {
                    gf += gsm[q*GR*GSTR + (0*JCOL+j)*GSTR + b];
                    gi += gsm[q*GR*GSTR + (1*JCOL+j)*GSTR + b];
                    go += gsm[q*GR*GSTR + (2*JCOL+j)*GSTR + b];
                    gc += gsm[q*GR*GSTR + (3*JCOL+j)*GSTR + b];
                }
            }
            float fg = sigmoidf_(gf);
            float ig = sigmoidf_(gi);
            float og = sigmoidf_(go);
            float cc = tanhf(gc);
            float cold = csm[tid];
            float cnew = fg * cold + ig * cc;
            csm[tid] = cnew;
            float h = og * tanhf(cnew);
            __stcg(hnext + b * HDIM + j0 + j, h);
            __stcs(hseq + ((size_t)t * BATCH + b) * HDIM + j0 + j, h);
            if (t == T_STEPS - 1) {
                hfin[b * HDIM + j0 + j] = h;
                cfin[b * HDIM + j0 + j] = cnew;
            }
        }

        // grid barrier between steps
        if (t < T_STEPS - 1) {
            __threadfence();
            __syncthreads();
            if (tid == 0) {
                unsigned target = base_epoch + (unsigned)(t + 1);
                unsigned old = atomicAdd(&g_bar_count, 1u);
                if (old == NCTA - 1) {
                    atomicExch(&g_bar_count, 0u);
                    __threadfence();
                    atomicAdd(&g_bar_epoch, 1u);
                } else {
                    while ((int)(*(volatile unsigned*)&g_bar_epoch - target) < 0) { }
                }
                __threadfence();
            }
            __syncthreads();
        }
    }
}

extern "C" void kernel_launch(void* const* d_in, const int* in_sizes, int n_in,
                              void* d_out, int out_size)
{
    (void)in_sizes; (void)n_in; (void)out_size;
    const float* x   = (const float*)d_in[0];
    const float* Wf  = (const float*)d_in[1];
    const float* bWf = (const float*)d_in[2];
    const float* Wi  = (const float*)d_in[3];
    const float* bWi = (const float*)d_in[4];
    const float* Wo  = (const float*)d_in[5];
    const float* bWo = (const float*)d_in[6];
    const float* Wc  = (const float*)d_in[7];
    const float* bWc = (const float*)d_in[8];
    const float* Uf  = (const float*)d_in[9];
    const float* bUf = (const float*)d_in[10];
    const float* Ui  = (const float*)d_in[11];
    const float* bUi = (const float*)d_in[12];
    const float* Uo  = (const float*)d_in[13];
    const float* bUo = (const float*)d_in[14];
    const float* Uc  = (const float*)d_in[15];
    const float* bUc = (const float*)d_in[16];

    size_t p1_smem = P1_FLOATS * sizeof(float);
    size_t p2_smem = P2_FLOATS * sizeof(float);
    cudaFuncSetAttribute(lstm_xw_kernel,
                         cudaFuncAttributeMaxDynamicSharedMemorySize, (int)p1_smem);
    cudaFuncSetAttribute(lstm_recur_kernel,
                         cudaFuncAttributeMaxDynamicSharedMemorySize, (int)p2_smem);

    dim3 g1(NCTA, T_STEPS / P1_TT);
    lstm_xw_kernel<<<g1, NTHR, p1_smem>>>(
        x, Wf, bWf, Wi, bWi, Wo, bWo, Wc, bWc, bUf, bUi, bUo, bUc);

    lstm_recur_kernel<<<NCTA, NTHR2, p2_smem>>>(Uf, Ui, Uo, Uc, (float*)d_out);
}

// round 5
// speedup vs baseline: 1.0689x; 1.0689x over previous
#include <cuda_runtime.h>
#include <cstdint>

#define T_STEPS 512
#define BATCH   64
#define IDIM    256
#define HDIM    512
#define NCTA    128
#define NTHR    256
#define NTHR2   512
#define JCOL    4
#define GR      16            // gate rows per CTA
#define GSTR    68            // gate-exchange row stride

typedef unsigned long long ull;

__device__ float g_xw[(size_t)T_STEPS * NCTA * GR * BATCH];   // [t][cta][row][b], bias folded
__device__ float g_hbuf[2][BATCH * HDIM];
__device__ unsigned int g_bar_count;
__device__ unsigned int g_bar_epoch;

__device__ __forceinline__ ull fma2(ull a, ull b, ull c) {
    ull d;
    asm("fma.rn.f32x2 %0, %1, %2, %3;" : "=l"(d) : "l"(a), "l"(b), "l"(c));
    return d;
}
__device__ __forceinline__ float hsum2(ull a) {
    return __uint_as_float((unsigned)(a & 0xffffffffu)) +
           __uint_as_float((unsigned)(a >> 32));
}
__device__ __forceinline__ float sigmoidf_(float v) {
    return __fdividef(1.0f, 1.0f + __expf(-v));
}
__device__ __forceinline__ void cpasync16(uint32_t dst, const void* src) {
    asm volatile("cp.async.cg.shared.global [%0], [%1], 16;" :: "r"(dst), "l"(src));
}
#define CP_COMMIT() asm volatile("cp.async.commit_group;" ::: "memory")
#define CP_WAIT(n)  asm volatile("cp.async.wait_group %0;" :: "n"(n) : "memory")

__device__ __forceinline__ unsigned atom_add_acqrel_gpu(unsigned* p, unsigned v) {
    unsigned old;
    asm volatile("atom.add.acq_rel.gpu.u32 %0, [%1], %2;" : "=r"(old) : "l"(p), "r"(v) : "memory");
    return old;
}
__device__ __forceinline__ void atom_add_release_gpu(unsigned* p, unsigned v) {
    unsigned old;
    asm volatile("atom.add.release.gpu.u32 %0, [%1], %2;" : "=r"(old) : "l"(p), "r"(v) : "memory");
    (void)old;
}
__device__ __forceinline__ unsigned ld_acquire_gpu(const unsigned* p) {
    unsigned v;
    asm volatile("ld.acquire.gpu.u32 %0, [%1];" : "=r"(v) : "l"(p) : "memory");
    return v;
}
__device__ __forceinline__ void st_relaxed_gpu(unsigned* p, unsigned v) {
    asm volatile("st.relaxed.gpu.u32 [%0], %1;" :: "l"(p), "r"(v) : "memory");
}

// 16-wide fma2 update: one 4-float k-slab of w0/w1 against 4 activation rows
#define MACBLK(kkv)                                                        \
    {                                                                      \
        ulonglong2 w0v = *(const ulonglong2*)(w0 + (kkv));                 \
        ulonglong2 w1v = *(const ulonglong2*)(w1 + (kkv));                 \
        ulonglong2 av;                                                     \
        av = *(const ulonglong2*)(a0p + (kkv));                            \
        A0  = fma2(w0v.x, av.x, A0);  A1  = fma2(w0v.y, av.y, A1);         \
        A2  = fma2(w1v.x, av.x, A2);  A3  = fma2(w1v.y, av.y, A3);         \
        av = *(const ulonglong2*)(a1p + (kkv));                            \
        A4  = fma2(w0v.x, av.x, A4);  A5  = fma2(w0v.y, av.y, A5);         \
        A6  = fma2(w1v.x, av.x, A6);  A7  = fma2(w1v.y, av.y, A7);         \
        av = *(const ulonglong2*)(a2p + (kkv));                            \
        A8  = fma2(w0v.x, av.x, A8);  A9  = fma2(w0v.y, av.y, A9);         \
        A10 = fma2(w1v.x, av.x, A10); A11 = fma2(w1v.y, av.y, A11);        \
        av = *(const ulonglong2*)(a3p + (kkv));                            \
        A12 = fma2(w0v.x, av.x, A12); A13 = fma2(w0v.y, av.y, A13);        \
        A14 = fma2(w1v.x, av.x, A14); A15 = fma2(w1v.y, av.y, A15);        \
    }

// ============================================================================
// Phase 1: xw[t] = x_t @ Wall^T + (bW + bU), fully parallel.
// ============================================================================
#define P1_TT   16
#define P1_WXS  260
#define P1_CKP  132
#define P1_OFF_WX   0
#define P1_OFF_ASH  (P1_OFF_WX + GR * P1_WXS)
#define P1_OFF_GSM  (P1_OFF_ASH + 2 * BATCH * P1_CKP)
#define P1_OFF_BS   (P1_OFF_GSM + 2 * GR * GSTR)
#define P1_FLOATS   (P1_OFF_BS + GR)

__global__ void __launch_bounds__(NTHR, 2)
lstm_xw_kernel(const float* __restrict__ x,
               const float* __restrict__ Wf, const float* __restrict__ bWf,
               const float* __restrict__ Wi, const float* __restrict__ bWi,
               const float* __restrict__ Wo, const float* __restrict__ bWo,
               const float* __restrict__ Wc, const float* __restrict__ bWc,
               const float* __restrict__ bUf, const float* __restrict__ bUi,
               const float* __restrict__ bUo, const float* __restrict__ bUc)
{
    extern __shared__ float sm[];
    float* Wx  = sm + P1_OFF_WX;
    float* ash = sm + P1_OFF_ASH;
    float* gsm = sm + P1_OFF_GSM;
    float* bsm = sm + P1_OFF_BS;

    const int tid = threadIdx.x;
    const int kh  = tid >> 7;
    const int tl  = tid & 127;
    const int cg  = tl & 7;
    const int bg  = tl >> 3;
    const int jg  = blockIdx.x;
    const int j0  = jg * JCOL;
    const int t0  = blockIdx.y * P1_TT;

    {
        const float* Wg[4]  = {Wf, Wi, Wo, Wc};
        const float* bWg[4] = {bWf, bWi, bWo, bWc};
        const float* bUg[4] = {bUf, bUi, bUo, bUc};
        for (int idx = tid; idx < GR * IDIM; idx += NTHR) {
            int row = idx >> 8, k = idx & (IDIM - 1);
            int gate = row >> 2, j = row & 3;
            Wx[row * P1_WXS + k] = Wg[gate][(j0 + j) * IDIM + k];
        }
        if (tid < GR) {
            int gate = tid >> 2, j = tid & 3;
            bsm[tid] = bWg[gate][j0 + j] + bUg[gate][j0 + j];
        }
    }
    __syncthreads();

    const float* w0b = Wx + cg * P1_WXS + kh * 64;
    const float* w1b = Wx + (cg + 8) * P1_WXS + kh * 64;

    for (int tt = 0; tt < P1_TT; ++tt) {
        const int t = t0 + tt;
        const float* xt = x + (size_t)t * BATCH * IDIM;

        #pragma unroll
        for (int r = 0; r < 8; ++r) {
            int idx = tid + r * NTHR;
            int b = idx >> 5, q = idx & 31;
            float4 v = __ldg(reinterpret_cast<const float4*>(xt + b * IDIM + q * 4));
            *reinterpret_cast<float4*>(ash + b * P1_CKP + q * 4) = v;
        }
        __syncthreads();

        ull A0=0,A1=0,A2=0,A3=0,A4=0,A5=0,A6=0,A7=0;
        ull A8=0,A9=0,A10=0,A11=0,A12=0,A13=0,A14=0,A15=0;

        #pragma unroll
        for (int r = 0; r < 8; ++r) {
            int idx = tid + r * NTHR;
            int b = idx >> 5, q = idx & 31;
            float4 v = __ldg(reinterpret_cast<const float4*>(xt + b * IDIM + 128 + q * 4));
            *reinterpret_cast<float4*>(ash + BATCH * P1_CKP + b * P1_CKP + q * 4) = v;
        }
        {
            // rows {bg, bg+16, bg+32, bg+48}: conflict-free (stride 132 ≡ 4 mod 32)
            const float* abase = ash + kh * 64;
            const float* a0p = abase + (bg +  0) * P1_CKP;
            const float* a1p = abase + (bg + 16) * P1_CKP;
            const float* a2p = abase + (bg + 32) * P1_CKP;
            const float* a3p = abase + (bg + 48) * P1_CKP;
            const float* w0 = w0b;
            const float* w1 = w1b;
            #pragma unroll
            for (int kk = 0; kk < 64; kk += 4) MACBLK(kk)
        }
        __syncthreads();
        {
            const float* abase = ash + BATCH * P1_CKP + kh * 64;
            const float* a0p = abase + (bg +  0) * P1_CKP;
            const float* a1p = abase + (bg + 16) * P1_CKP;
            const float* a2p = abase + (bg + 32) * P1_CKP;
            const float* a3p = abase + (bg + 48) * P1_CKP;
            const float* w0 = w0b + 128;
            const float* w1 = w1b + 128;
            #pragma unroll
            for (int kk = 0; kk < 64; kk += 4) MACBLK(kk)
        }
        {
            float* g0 = gsm + kh * GR * GSTR + cg * GSTR + bg;
            float* g1 = gsm + kh * GR * GSTR + (cg + 8) * GSTR + bg;
            g0[ 0] = hsum2(A0)  + hsum2(A1);
            g1[ 0] = hsum2(A2)  + hsum2(A3);
            g0[16] = hsum2(A4)  + hsum2(A5);
            g1[16] = hsum2(A6)  + hsum2(A7);
            g0[32] = hsum2(A8)  + hsum2(A9);
            g1[32] = hsum2(A10) + hsum2(A11);
            g0[48] = hsum2(A12) + hsum2(A13);
            g1[48] = hsum2(A14) + hsum2(A15);
        }
        __syncthreads();
        {
            int row = tid >> 4;
            int b4  = (tid & 15) * 4;
            float4 p0 = *reinterpret_cast<float4*>(gsm + row * GSTR + b4);
            float4 p1 = *reinterpret_cast<float4*>(gsm + GR * GSTR + row * GSTR + b4);
            float bb = bsm[row];
            float4 o;
            o.x = p0.x + p1.x + bb;
            o.y = p0.y + p1.y + bb;
            o.z = p0.z + p1.z + bb;
            o.w = p0.w + p1.w + bb;
            *reinterpret_cast<float4*>(g_xw + (((size_t)t * NCTA + jg) * GR + row) * BATCH + b4) = o;
        }
        __syncthreads();
    }
}

// ============================================================================
// Phase 2: persistent recurrence, 512 threads, conflict-free LDS, cheap barrier.
// ============================================================================
#define P2_WHS  516
#define P2_CKP  260
#define P2_OFF_WH   0
#define P2_OFF_ASH  (P2_OFF_WH + GR * P2_WHS)            // 8256
#define P2_OFF_GSM  (P2_OFF_ASH + 2 * BATCH * P2_CKP)    // +33280
#define P2_OFF_XW   (P2_OFF_GSM + 4 * GR * GSTR)         // +4352
#define P2_OFF_CSM  (P2_OFF_XW + 2 * GR * GSTR)          // +2176 (double-buffered)
#define P2_OFF_EB   (P2_OFF_CSM + 256)
#define P2_FLOATS   (P2_OFF_EB + 4)

__global__ void __launch_bounds__(NTHR2, 1)
lstm_recur_kernel(const float* __restrict__ Uf, const float* __restrict__ Ui,
                  const float* __restrict__ Uo, const float* __restrict__ Uc,
                  float* __restrict__ out)
{
    extern __shared__ float sm[];
    float* Wh   = sm + P2_OFF_WH;
    float* ash  = sm + P2_OFF_ASH;
    float* gsm  = sm + P2_OFF_GSM;
    float* xwsm = sm + P2_OFF_XW;
    float* csm  = sm + P2_OFF_CSM;
    unsigned* ebase = (unsigned*)(sm + P2_OFF_EB);

    const int tid = threadIdx.x;
    const int kq  = tid >> 7;            // K-quarter 0..3
    const int tl  = tid & 127;
    const int cg  = tl & 7;
    const int bg  = tl >> 3;
    const int j0  = blockIdx.x * JCOL;
    // chunk order stagger: odd CTAs do K[256:512] first
    const int cofs0 = (blockIdx.x & 1) ? 256 : 0;
    const int cofs1 = 256 - cofs0;

    const uint32_t sm_u32 = (uint32_t)__cvta_generic_to_shared(sm);
    const uint32_t ash_u32  = sm_u32 + P2_OFF_ASH * 4;
    const uint32_t xwsm_u32 = sm_u32 + P2_OFF_XW * 4;

    {
        const float* Ug[4] = {Uf, Ui, Uo, Uc};
        for (int idx = tid; idx < GR * HDIM; idx += NTHR2) {
            int row = idx >> 9, k = idx & (HDIM - 1);
            int gate = row >> 2, j = row & 3;
            Wh[row * P2_WHS + k] = Ug[gate][(j0 + j) * HDIM + k];
        }
        if (tid < 256) csm[tid] = 0.0f;
        if (tid == 0) *ebase = *(volatile unsigned*)&g_bar_epoch;
        // xw block for t=0 into buffer 0
        if (tid < 256) {
            int row = tid >> 4;
            int b4  = (tid & 15) * 4;
            const float* src = g_xw + (size_t)blockIdx.x * GR * BATCH;
            float4 v = __ldg(reinterpret_cast<const float4*>(src + row * BATCH + b4));
            *reinterpret_cast<float4*>(xwsm + row * GSTR + b4) = v;
        }
    }
    __syncthreads();
    const unsigned base_epoch = *ebase;

    float* hseq = out;
    float* hfin = out + (size_t)T_STEPS * BATCH * HDIM;
    float* cfin = hfin + BATCH * HDIM;

    const float* w0b = Wh + cg * P2_WHS + kq * 64;
    const float* w1b = Wh + (cg + 8) * P2_WHS + kq * 64;
    const float* xwblk0 = g_xw + (size_t)blockIdx.x * GR * BATCH;

    for (int t = 0; t < T_STEPS; ++t) {
        if (t > 0) {
            const float* hprev = g_hbuf[t & 1];

            // group A: first chunk (K offset cofs0) into ash buf0
            #pragma unroll
            for (int r = 0; r < 8; ++r) {
                int idx = tid + r * NTHR2;
                int b = idx >> 6, q = idx & 63;
                cpasync16(ash_u32 + (b * P2_CKP + q * 4) * 4,
                          hprev + b * HDIM + cofs0 + q * 4);
            }
            CP_COMMIT();
            // group B: second chunk (K offset cofs1) into ash buf1
            #pragma unroll
            for (int r = 0; r < 8; ++r) {
                int idx = tid + r * NTHR2;
                int b = idx >> 6, q = idx & 63;
                cpasync16(ash_u32 + (BATCH * P2_CKP + b * P2_CKP + q * 4) * 4,
                          hprev + b * HDIM + cofs1 + q * 4);
            }
            CP_COMMIT();

            CP_WAIT(1);                 // xw(t) prefetch + chunk A landed
            __syncthreads();

            ull A0=0,A1=0,A2=0,A3=0,A4=0,A5=0,A6=0,A7=0;
            ull A8=0,A9=0,A10=0,A11=0,A12=0,A13=0,A14=0,A15=0;

            // compute first chunk while second streams in
            {
                // rows {bg, bg+16, bg+32, bg+48}: stride 260 ≡ 4 mod 32 → conflict-free
                const float* abase = ash + kq * 64;
                const float* a0p = abase + (bg +  0) * P2_CKP;
                const float* a1p = abase + (bg + 16) * P2_CKP;
                const float* a2p = abase + (bg + 32) * P2_CKP;
                const float* a3p = abase + (bg + 48) * P2_CKP;
                const float* w0 = w0b + cofs0;
                const float* w1 = w1b + cofs0;
                #pragma unroll
                for (int kk = 0; kk < 64; kk += 4) MACBLK(kk)
            }
            CP_WAIT(0);
            __syncthreads();
            // compute second chunk
            {
                const float* abase = ash + BATCH * P2_CKP + kq * 64;
                const float* a0p = abase + (bg +  0) * P2_CKP;
                const float* a1p = abase + (bg + 16) * P2_CKP;
                const float* a2p = abase + (bg + 32) * P2_CKP;
                const float* a3p = abase + (bg + 48) * P2_CKP;
                const float* w0 = w0b + cofs1;
                const float* w1 = w1b + cofs1;
                #pragma unroll
                for (int kk = 0; kk < 64; kk += 4) MACBLK(kk)
            }
            // per-quarter partial gate sums
            {
                float* g0 = gsm + kq * GR * GSTR + cg * GSTR + bg;
                float* g1 = gsm + kq * GR * GSTR + (cg + 8) * GSTR + bg;
                g0[ 0] = hsum2(A0)  + hsum2(A1);
                g1[ 0] = hsum2(A2)  + hsum2(A3);
                g0[16] = hsum2(A4)  + hsum2(A5);
                g1[16] = hsum2(A6)  + hsum2(A7);
                g0[32] = hsum2(A8)  + hsum2(A9);
                g1[32] = hsum2(A10) + hsum2(A11);
                g0[48] = hsum2(A12) + hsum2(A13);
                g1[48] = hsum2(A14) + hsum2(A15);
            }
            __syncthreads();
        }

        // elementwise LSTM update (tid < 256: one (j,b) element each)
        float* hnext = g_hbuf[(t + 1) & 1];
        const float* xwb = xwsm + (t & 1) * GR * GSTR;
        if (tid < 256) {
            int j = tid & 3;
            int b = tid >> 2;
            float gf = xwb[(0*JCOL+j)*GSTR + b];
            float gi = xwb[(1*JCOL+j)*GSTR + b];
            float go = xwb[(2*JCOL+j)*GSTR + b];
            float gc = xwb[(3*JCOL+j)*GSTR + b];
            if (t > 0) {
                #pragma unroll
                for (int q = 0; q < 4; ++q) {
                    gf += gsm[q*GR*GSTR + (0*JCOL+j)*GSTR + b];
                    gi += gsm[q*GR*GSTR + (1*JCOL+j)*GSTR + b];
                    go += gsm[q*GR*GSTR + (2*JCOL+j)*GSTR + b];
                    gc += gsm[q*GR*GSTR + (3*JCOL+j)*GSTR + b];
                }
            }
            float fg = sigmoidf_(gf);
            float ig = sigmoidf_(gi);
            float og = sigmoidf_(go);
            float cc = tanhf(gc);
            float cold = csm[tid];
            float cnew = fg * cold + ig * cc;
            csm[tid] = cnew;
            float h = og * tanhf(cnew);
            __stcg(hnext + b * HDIM + j0 + j, h);
            __stcs(hseq + ((size_t)t * BATCH + b) * HDIM + j0 + j, h);
            if (t == T_STEPS - 1) {
                hfin[b * HDIM + j0 + j] = h;
                cfin[b * HDIM + j0 + j] = cnew;
            }
        }

        if (t < T_STEPS - 1) {
            // prefetch next step's xw block (independent of h) into other buffer
            if (tid < 256) {
                int row = tid >> 4;
                int b4  = (tid & 15) * 4;
                const float* src = xwblk0 + (size_t)(t + 1) * NCTA * GR * BATCH;
                cpasync16(xwsm_u32 + (((t + 1) & 1) * GR * GSTR + row * GSTR + b4) * 4,
                          src + row * BATCH + b4);
            }
            CP_COMMIT();

            // grid barrier: syncthreads + tid0 release/acquire atomics
            __syncthreads();
            if (tid == 0) {
                unsigned old = atom_add_acqrel_gpu(&g_bar_count, 1u);
                if (old == NCTA - 1) {
                    st_relaxed_gpu(&g_bar_count, 0u);
                    atom_add_release_gpu(&g_bar_epoch, 1u);
                } else {
                    unsigned target = base_epoch + (unsigned)(t + 1);
                    while ((int)(ld_acquire_gpu(&g_bar_epoch) - target) < 0) { }
                }
            }
            __syncthreads();
        }
    }
}

extern "C" void kernel_launch(void* const* d_in, const int* in_sizes, int n_in,
                              void* d_out, int out_size)
{
    (void)in_sizes; (void)n_in; (void)out_size;
    const float* x   = (const float*)d_in[0];
    const float* Wf  = (const float*)d_in[1];
    const float* bWf = (const float*)d_in[2];
    const float* Wi  = (const float*)d_in[3];
    const float* bWi = (const float*)d_in[4];
    const float* Wo  = (const float*)d_in[5];
    const float* bWo = (const float*)d_in[6];
    const float* Wc  = (const float*)d_in[7];
    const float* bWc = (const float*)d_in[8];
    const float* Uf  = (const float*)d_in[9];
    const float* bUf = (const float*)d_in[10];
    const float* Ui  = (const float*)d_in[11];
    const float* bUi = (const float*)d_in[12];
    const float* Uo  = (const float*)d_in[13];
    const float* bUo = (const float*)d_in[14];
    const float* Uc  = (const float*)d_in[15];
    const float* bUc = (const float*)d_in[16];

    size_t p1_smem = P1_FLOATS * sizeof(float);
    size_t p2_smem = P2_FLOATS * sizeof(float);
    cudaFuncSetAttribute(lstm_xw_kernel,
                         cudaFuncAttributeMaxDynamicSharedMemorySize, (int)p1_smem);
    cudaFuncSetAttribute(lstm_recur_kernel,
                         cudaFuncAttributeMaxDynamicSharedMemorySize, (int)p2_smem);

    dim3 g1(NCTA, T_STEPS / P1_TT);
    lstm_xw_kernel<<<g1, NTHR, p1_smem>>>(
        x, Wf, bWf, Wi, bWi, Wo, bWo, Wc, bWc, bUf, bUi, bUo, bUc);

    lstm_recur_kernel<<<NCTA, NTHR2, p2_smem>>>(Uf, Ui, Uo, Uc, (float*)d_out);
}

// round 6
// speedup vs baseline: 1.0769x; 1.0075x over previous
#include <cuda_runtime.h>
#include <cstdint>

#define T_STEPS 512
#define BATCH   64
#define IDIM    256
#define HDIM    512
#define NCTA    128
#define NTHR    256
#define NTHR2   512
#define JCOL    4
#define GR      16            // gate rows per CTA
#define GSTR    68            // gate-exchange row stride

typedef unsigned long long ull;

__device__ float g_xw[(size_t)T_STEPS * NCTA * GR * BATCH];   // [t][cta][row][b], bias folded
__device__ float g_hbuf[2][BATCH * HDIM];
__device__ unsigned int g_bar_count;
__device__ unsigned int g_bar_epoch;

__device__ __forceinline__ ull fma2(ull a, ull b, ull c) {
    ull d;
    asm("fma.rn.f32x2 %0, %1, %2, %3;" : "=l"(d) : "l"(a), "l"(b), "l"(c));
    return d;
}
__device__ __forceinline__ float hsum2(ull a) {
    return __uint_as_float((unsigned)(a & 0xffffffffu)) +
           __uint_as_float((unsigned)(a >> 32));
}
__device__ __forceinline__ float sigmoidf_(float v) {
    return __fdividef(1.0f, 1.0f + __expf(-v));
}
__device__ __forceinline__ void cpasync16(uint32_t dst, const void* src) {
    asm volatile("cp.async.cg.shared.global [%0], [%1], 16;" :: "r"(dst), "l"(src));
}
#define CP_COMMIT() asm volatile("cp.async.commit_group;" ::: "memory")
#define CP_WAIT(n)  asm volatile("cp.async.wait_group %0;" :: "n"(n) : "memory")

__device__ __forceinline__ unsigned atom_add_acqrel_gpu(unsigned* p, unsigned v) {
    unsigned old;
    asm volatile("atom.add.acq_rel.gpu.u32 %0, [%1], %2;" : "=r"(old) : "l"(p), "r"(v) : "memory");
    return old;
}
__device__ __forceinline__ void atom_add_release_gpu(unsigned* p, unsigned v) {
    unsigned old;
    asm volatile("atom.add.release.gpu.u32 %0, [%1], %2;" : "=r"(old) : "l"(p), "r"(v) : "memory");
    (void)old;
}
__device__ __forceinline__ unsigned ld_acquire_gpu(const unsigned* p) {
    unsigned v;
    asm volatile("ld.acquire.gpu.u32 %0, [%1];" : "=r"(v) : "l"(p) : "memory");
    return v;
}
__device__ __forceinline__ void st_relaxed_gpu(unsigned* p, unsigned v) {
    asm volatile("st.relaxed.gpu.u32 [%0], %1;" :: "l"(p), "r"(v) : "memory");
}

// 16-wide fma2 update: one 4-float k-slab of w0/w1 against 4 activation rows
#define MACBLK(kkv)                                                        \
    {                                                                      \
        ulonglong2 w0v = *(const ulonglong2*)(w0 + (kkv));                 \
        ulonglong2 w1v = *(const ulonglong2*)(w1 + (kkv));                 \
        ulonglong2 av;                                                     \
        av = *(const ulonglong2*)(a0p + (kkv));                            \
        A0  = fma2(w0v.x, av.x, A0);  A1  = fma2(w0v.y, av.y, A1);         \
        A2  = fma2(w1v.x, av.x, A2);  A3  = fma2(w1v.y, av.y, A3);         \
        av = *(const ulonglong2*)(a1p + (kkv));                            \
        A4  = fma2(w0v.x, av.x, A4);  A5  = fma2(w0v.y, av.y, A5);         \
        A6  = fma2(w1v.x, av.x, A6);  A7  = fma2(w1v.y, av.y, A7);         \
        av = *(const ulonglong2*)(a2p + (kkv));                            \
        A8  = fma2(w0v.x, av.x, A8);  A9  = fma2(w0v.y, av.y, A9);         \
        A10 = fma2(w1v.x, av.x, A10); A11 = fma2(w1v.y, av.y, A11);        \
        av = *(const ulonglong2*)(a3p + (kkv));                            \
        A12 = fma2(w0v.x, av.x, A12); A13 = fma2(w0v.y, av.y, A13);        \
        A14 = fma2(w1v.x, av.x, A14); A15 = fma2(w1v.y, av.y, A15);        \
    }

// ============================================================================
// Phase 1: xw[t] = x_t @ Wall^T + (bW + bU), fully parallel.
// ============================================================================
#define P1_TT   16
#define P1_WXS  260
#define P1_CKP  132
#define P1_OFF_WX   0
#define P1_OFF_ASH  (P1_OFF_WX + GR * P1_WXS)
#define P1_OFF_GSM  (P1_OFF_ASH + 2 * BATCH * P1_CKP)
#define P1_OFF_BS   (P1_OFF_GSM + 2 * GR * GSTR)
#define P1_FLOATS   (P1_OFF_BS + GR)

__global__ void __launch_bounds__(NTHR, 2)
lstm_xw_kernel(const float* __restrict__ x,
               const float* __restrict__ Wf, const float* __restrict__ bWf,
               const float* __restrict__ Wi, const float* __restrict__ bWi,
               const float* __restrict__ Wo, const float* __restrict__ bWo,
               const float* __restrict__ Wc, const float* __restrict__ bWc,
               const float* __restrict__ bUf, const float* __restrict__ bUi,
               const float* __restrict__ bUo, const float* __restrict__ bUc)
{
    extern __shared__ float sm[];
    float* Wx  = sm + P1_OFF_WX;
    float* ash = sm + P1_OFF_ASH;
    float* gsm = sm + P1_OFF_GSM;
    float* bsm = sm + P1_OFF_BS;

    const int tid = threadIdx.x;
    const int kh  = tid >> 7;
    const int tl  = tid & 127;
    const int cg  = tl & 7;
    const int bg  = tl >> 3;
    const int jg  = blockIdx.x;
    const int j0  = jg * JCOL;
    const int t0  = blockIdx.y * P1_TT;

    {
        const float* Wg[4]  = {Wf, Wi, Wo, Wc};
        const float* bWg[4] = {bWf, bWi, bWo, bWc};
        const float* bUg[4] = {bUf, bUi, bUo, bUc};
        for (int idx = tid; idx < GR * IDIM; idx += NTHR) {
            int row = idx >> 8, k = idx & (IDIM - 1);
            int gate = row >> 2, j = row & 3;
            Wx[row * P1_WXS + k] = Wg[gate][(j0 + j) * IDIM + k];
        }
        if (tid < GR) {
            int gate = tid >> 2, j = tid & 3;
            bsm[tid] = bWg[gate][j0 + j] + bUg[gate][j0 + j];
        }
    }
    __syncthreads();

    const float* w0b = Wx + cg * P1_WXS + kh * 64;
    const float* w1b = Wx + (cg + 8) * P1_WXS + kh * 64;

    for (int tt = 0; tt < P1_TT; ++tt) {
        const int t = t0 + tt;
        const float* xt = x + (size_t)t * BATCH * IDIM;

        #pragma unroll
        for (int r = 0; r < 8; ++r) {
            int idx = tid + r * NTHR;
            int b = idx >> 5, q = idx & 31;
            float4 v = __ldg(reinterpret_cast<const float4*>(xt + b * IDIM + q * 4));
            *reinterpret_cast<float4*>(ash + b * P1_CKP + q * 4) = v;
        }
        __syncthreads();

        ull A0=0,A1=0,A2=0,A3=0,A4=0,A5=0,A6=0,A7=0;
        ull A8=0,A9=0,A10=0,A11=0,A12=0,A13=0,A14=0,A15=0;

        #pragma unroll
        for (int r = 0; r < 8; ++r) {
            int idx = tid + r * NTHR;
            int b = idx >> 5, q = idx & 31;
            float4 v = __ldg(reinterpret_cast<const float4*>(xt + b * IDIM + 128 + q * 4));
            *reinterpret_cast<float4*>(ash + BATCH * P1_CKP + b * P1_CKP + q * 4) = v;
        }
        {
            // rows {bg, bg+16, bg+32, bg+48}: conflict-free (stride 132 ≡ 4 mod 32)
            const float* abase = ash + kh * 64;
            const float* a0p = abase + (bg +  0) * P1_CKP;
            const float* a1p = abase + (bg + 16) * P1_CKP;
            const float* a2p = abase + (bg + 32) * P1_CKP;
            const float* a3p = abase + (bg + 48) * P1_CKP;
            const float* w0 = w0b;
            const float* w1 = w1b;
            #pragma unroll
            for (int kk = 0; kk < 64; kk += 4) MACBLK(kk)
        }
        __syncthreads();
        {
            const float* abase = ash + BATCH * P1_CKP + kh * 64;
            const float* a0p = abase + (bg +  0) * P1_CKP;
            const float* a1p = abase + (bg + 16) * P1_CKP;
            const float* a2p = abase + (bg + 32) * P1_CKP;
            const float* a3p = abase + (bg + 48) * P1_CKP;
            const float* w0 = w0b + 128;
            const float* w1 = w1b + 128;
            #pragma unroll
            for (int kk = 0; kk < 64; kk += 4) MACBLK(kk)
        }
        {
            float* g0 = gsm + kh * GR * GSTR + cg * GSTR + bg;
            float* g1 = gsm + kh * GR * GSTR + (cg + 8) * GSTR + bg;
            g0[ 0] = hsum2(A0)  + hsum2(A1);
            g1[ 0] = hsum2(A2)  + hsum2(A3);
            g0[16] = hsum2(A4)  + hsum2(A5);
            g1[16] = hsum2(A6)  + hsum2(A7);
            g0[32] = hsum2(A8)  + hsum2(A9);
            g1[32] = hsum2(A10) + hsum2(A11);
            g0[48] = hsum2(A12) + hsum2(A13);
            g1[48] = hsum2(A14) + hsum2(A15);
        }
        __syncthreads();
        {
            int row = tid >> 4;
            int b4  = (tid & 15) * 4;
            float4 p0 = *reinterpret_cast<float4*>(gsm + row * GSTR + b4);
            float4 p1 = *reinterpret_cast<float4*>(gsm + GR * GSTR + row * GSTR + b4);
            float bb = bsm[row];
            float4 o;
            o.x = p0.x + p1.x + bb;
            o.y = p0.y + p1.y + bb;
            o.z = p0.z + p1.z + bb;
            o.w = p0.w + p1.w + bb;
            *reinterpret_cast<float4*>(g_xw + (((size_t)t * NCTA + jg) * GR + row) * BATCH + b4) = o;
        }
        __syncthreads();
    }
}

// ============================================================================
// Phase 2: persistent recurrence, 512 threads, conflict-free LDS, cheap barrier.
// ============================================================================
#define P2_WHS  516
#define P2_CKP  260
#define P2_OFF_WH   0
#define P2_OFF_ASH  (P2_OFF_WH + GR * P2_WHS)            // 8256
#define P2_OFF_GSM  (P2_OFF_ASH + 2 * BATCH * P2_CKP)    // +33280
#define P2_OFF_XW   (P2_OFF_GSM + 4 * GR * GSTR)         // +4352
#define P2_OFF_CSM  (P2_OFF_XW + 2 * GR * GSTR)          // +2176 (double-buffered)
#define P2_OFF_EB   (P2_OFF_CSM + 256)
#define P2_FLOATS   (P2_OFF_EB + 4)

__global__ void __launch_bounds__(NTHR2, 1)
lstm_recur_kernel(const float* __restrict__ Uf, const float* __restrict__ Ui,
                  const float* __restrict__ Uo, const float* __restrict__ Uc,
                  float* __restrict__ out)
{
    extern __shared__ float sm[];
    float* Wh   = sm + P2_OFF_WH;
    float* ash  = sm + P2_OFF_ASH;
    float* gsm  = sm + P2_OFF_GSM;
    float* xwsm = sm + P2_OFF_XW;
    float* csm  = sm + P2_OFF_CSM;
    unsigned* ebase = (unsigned*)(sm + P2_OFF_EB);

    const int tid = threadIdx.x;
    const int kq  = tid >> 7;            // K-quarter 0..3
    const int tl  = tid & 127;
    const int cg  = tl & 7;
    const int bg  = tl >> 3;
    const int j0  = blockIdx.x * JCOL;
    // chunk order stagger: odd CTAs do K[256:512] first
    const int cofs0 = (blockIdx.x & 1) ? 256 : 0;
    const int cofs1 = 256 - cofs0;

    const uint32_t sm_u32 = (uint32_t)__cvta_generic_to_shared(sm);
    const uint32_t ash_u32  = sm_u32 + P2_OFF_ASH * 4;
    const uint32_t xwsm_u32 = sm_u32 + P2_OFF_XW * 4;

    {
        const float* Ug[4] = {Uf, Ui, Uo, Uc};
        for (int idx = tid; idx < GR * HDIM; idx += NTHR2) {
            int row = idx >> 9, k = idx & (HDIM - 1);
            int gate = row >> 2, j = row & 3;
            Wh[row * P2_WHS + k] = Ug[gate][(j0 + j) * HDIM + k];
        }
        if (tid < 256) csm[tid] = 0.0f;
        if (tid == 0) *ebase = *(volatile unsigned*)&g_bar_epoch;
        // xw block for t=0 into buffer 0
        if (tid < 256) {
            int row = tid >> 4;
            int b4  = (tid & 15) * 4;
            const float* src = g_xw + (size_t)blockIdx.x * GR * BATCH;
            float4 v = __ldg(reinterpret_cast<const float4*>(src + row * BATCH + b4));
            *reinterpret_cast<float4*>(xwsm + row * GSTR + b4) = v;
        }
    }
    __syncthreads();
    const unsigned base_epoch = *ebase;

    float* hseq = out;
    float* hfin = out + (size_t)T_STEPS * BATCH * HDIM;
    float* cfin = hfin + BATCH * HDIM;

    const float* w0b = Wh + cg * P2_WHS + kq * 64;
    const float* w1b = Wh + (cg + 8) * P2_WHS + kq * 64;
    const float* xwblk0 = g_xw + (size_t)blockIdx.x * GR * BATCH;

    for (int t = 0; t < T_STEPS; ++t) {
        if (t > 0) {
            const float* hprev = g_hbuf[t & 1];

            // group A: first chunk (K offset cofs0) into ash buf0
            #pragma unroll
            for (int r = 0; r < 8; ++r) {
                int idx = tid + r * NTHR2;
                int b = idx >> 6, q = idx & 63;
                cpasync16(ash_u32 + (b * P2_CKP + q * 4) * 4,
                          hprev + b * HDIM + cofs0 + q * 4);
            }
            CP_COMMIT();
            // group B: second chunk (K offset cofs1) into ash buf1
            #pragma unroll
            for (int r = 0; r < 8; ++r) {
                int idx = tid + r * NTHR2;
                int b = idx >> 6, q = idx & 63;
                cpasync16(ash_u32 + (BATCH * P2_CKP + b * P2_CKP + q * 4) * 4,
                          hprev + b * HDIM + cofs1 + q * 4);
            }
            CP_COMMIT();

            CP_WAIT(1);                 // xw(t) prefetch + chunk A landed
            __syncthreads();

            ull A0=0,A1=0,A2=0,A3=0,A4=0,A5=0,A6=0,A7=0;
            ull A8=0,A9=0,A10=0,A11=0,A12=0,A13=0,A14=0,A15=0;

            // compute first chunk while second streams in
            {
                // rows {bg, bg+16, bg+32, bg+48}: stride 260 ≡ 4 mod 32 → conflict-free
                const float* abase = ash + kq * 64;
                const float* a0p = abase + (bg +  0) * P2_CKP;
                const float* a1p = abase + (bg + 16) * P2_CKP;
                const float* a2p = abase + (bg + 32) * P2_CKP;
                const float* a3p = abase + (bg + 48) * P2_CKP;
                const float* w0 = w0b + cofs0;
                const float* w1 = w1b + cofs0;
                #pragma unroll
                for (int kk = 0; kk < 64; kk += 4) MACBLK(kk)
            }
            CP_WAIT(0);
            __syncthreads();
            // compute second chunk
            {
                const float* abase = ash + BATCH * P2_CKP + kq * 64;
                const float* a0p = abase + (bg +  0) * P2_CKP;
                const float* a1p = abase + (bg + 16) * P2_CKP;
                const float* a2p = abase + (bg + 32) * P2_CKP;
                const float* a3p = abase + (bg + 48) * P2_CKP;
                const float* w0 = w0b + cofs1;
                const float* w1 = w1b + cofs1;
                #pragma unroll
                for (int kk = 0; kk < 64; kk += 4) MACBLK(kk)
            }
            // per-quarter partial gate sums
            {
                float* g0 = gsm + kq * GR * GSTR + cg * GSTR + bg;
                float* g1 = gsm + kq * GR * GSTR + (cg + 8) * GSTR + bg;
                g0[ 0] = hsum2(A0)  + hsum2(A1);
                g1[ 0] = hsum2(A2)  + hsum2(A3);
                g0[16] = hsum2(A4)  + hsum2(A5);
                g1[16] = hsum2(A6)  + hsum2(A7);
                g0[32] = hsum2(A8)  + hsum2(A9);
                g1[32] = hsum2(A10) + hsum2(A11);
                g0[48] = hsum2(A12) + hsum2(A13);
                g1[48] = hsum2(A14) + hsum2(A15);
            }
            __syncthreads();
        }

        // elementwise LSTM update (tid < 256: one (j,b) element each)
        float* hnext = g_hbuf[(t + 1) & 1];
        const float* xwb = xwsm + (t & 1) * GR * GSTR;
        if (tid < 256) {
            int j = tid & 3;
            int b = tid >> 2;
            float gf = xwb[(0*JCOL+j)*GSTR + b];
            float gi = xwb[(1*JCOL+j)*GSTR + b];
            float go = xwb[(2*JCOL+j)*GSTR + b];
            float gc = xwb[(3*JCOL+j)*GSTR + b];
            if (t > 0) {
                #pragma unroll
                for (int q = 0; q < 4; ++q) {
                    gf += gsm[q*GR*GSTR + (0*JCOL+j)*GSTR + b];
                    gi += gsm[q*GR*GSTR + (1*JCOL+j)*GSTR + b];
                    go += gsm[q*GR*GSTR + (2*JCOL+j)*GSTR + b];
                    gc += gsm[q*GR*GSTR + (3*JCOL+j)*GSTR + b];
                }
            }
            float fg = sigmoidf_(gf);
            float ig = sigmoidf_(gi);
            float og = sigmoidf_(go);
            float cc = tanhf(gc);
            float cold = csm[tid];
            float cnew = fg * cold + ig * cc;
            csm[tid] = cnew;
            float h = og * tanhf(cnew);
            __stcg(hnext + b * HDIM + j0 + j, h);
            __stcs(hseq + ((size_t)t * BATCH + b) * HDIM + j0 + j, h);
            if (t == T_STEPS - 1) {
                hfin[b * HDIM + j0 + j] = h;
                cfin[b * HDIM + j0 + j] = cnew;
            }
        }

        if (t < T_STEPS - 1) {
            // prefetch next step's xw block (independent of h) into other buffer
            if (tid < 256) {
                int row = tid >> 4;
                int b4  = (tid & 15) * 4;
                const float* src = xwblk0 + (size_t)(t + 1) * NCTA * GR * BATCH;
                cpasync16(xwsm_u32 + (((t + 1) & 1) * GR * GSTR + row * GSTR + b4) * 4,
                          src + row * BATCH + b4);
            }
            CP_COMMIT();

            // grid barrier: syncthreads + tid0 release/acquire atomics
            __syncthreads();
            if (tid == 0) {
                unsigned old = atom_add_acqrel_gpu(&g_bar_count, 1u);
                if (old == NCTA - 1) {
                    st_relaxed_gpu(&g_bar_count, 0u);
                    atom_add_release_gpu(&g_bar_epoch, 1u);
                } else {
                    unsigned target = base_epoch + (unsigned)(t + 1);
                    while ((int)(ld_acquire_gpu(&g_bar_epoch) - target) < 0) { }
                }
            }
            __syncthreads();
        }
    }
}

extern "C" void kernel_launch(void* const* d_in, const int* in_sizes, int n_in,
                              void* d_out, int out_size)
{
    (void)in_sizes; (void)n_in; (void)out_size;
    const float* x   = (const float*)d_in[0];
    const float* Wf  = (const float*)d_in[1];
    const float* bWf = (const float*)d_in[2];
    const float* Wi  = (const float*)d_in[3];
    const float* bWi = (const float*)d_in[4];
    const float* Wo  = (const float*)d_in[5];
    const float* bWo = (const float*)d_in[6];
    const float* Wc  = (const float*)d_in[7];
    const float* bWc = (const float*)d_in[8];
    const float* Uf  = (const float*)d_in[9];
    const float* bUf = (const float*)d_in[10];
    const float* Ui  = (const float*)d_in[11];
    const float* bUi = (const float*)d_in[12];
    const float* Uo  = (const float*)d_in[13];
    const float* bUo = (const float*)d_in[14];
    const float* Uc  = (const float*)d_in[15];
    const float* bUc = (const float*)d_in[16];

    size_t p1_smem = P1_FLOATS * sizeof(float);
    size_t p2_smem = P2_FLOATS * sizeof(float);
    cudaFuncSetAttribute(lstm_xw_kernel,
                         cudaFuncAttributeMaxDynamicSharedMemorySize, (int)p1_smem);
    cudaFuncSetAttribute(lstm_recur_kernel,
                         cudaFuncAttributeMaxDynamicSharedMemorySize, (int)p2_smem);

    dim3 g1(NCTA, T_STEPS / P1_TT);
    lstm_xw_kernel<<<g1, NTHR, p1_smem>>>(
        x, Wf, bWf, Wi, bWi, Wo, bWo, Wc, bWc, bUf, bUi, bUo, bUc);

    lstm_recur_kernel<<<NCTA, NTHR2, p2_smem>>>(Uf, Ui, Uo, Uc, (float*)d_out);
}

// round 8
// speedup vs baseline: 1.2140x; 1.1273x over previous
#include <cuda_runtime.h>
#include <cstdint>

#define T_STEPS 512
#define BATCH   64
#define IDIM    256
#define HDIM    512
#define NCTA    128
#define NTHR    256
#define NTHR2   512
#define JCOL    4
#define GR      16
#define GSTR    68
#define HPAD    260           // padded h row stride (floats): 4 mod 32, 16B aligned

typedef unsigned long long ull;

// ---- persistent device scratch ----
__device__ float g_xw[(size_t)T_STEPS * NCTA * GR * BATCH];   // [t][jg][row16][b]
__device__ float g_h0[2][BATCH * HPAD];                       // h cols   0..255, padded rows
__device__ float g_h1[2][BATCH * HPAD];                       // h cols 256..511, padded rows
__device__ unsigned int g_bar_count;
__device__ unsigned int g_bar_epoch;

// ---------------- helpers ----------------
__device__ __forceinline__ ull fma2(ull a, ull b, ull c) {
    ull d;
    asm("fma.rn.f32x2 %0, %1, %2, %3;" : "=l"(d) : "l"(a), "l"(b), "l"(c));
    return d;
}
__device__ __forceinline__ float hsum2(ull a) {
    return __uint_as_float((unsigned)(a & 0xffffffffu)) +
           __uint_as_float((unsigned)(a >> 32));
}
__device__ __forceinline__ float sigmoidf_(float v) {
    return __fdividef(1.0f, 1.0f + __expf(-v));
}
__device__ __forceinline__ unsigned atom_add_acqrel_gpu(unsigned* p, unsigned v) {
    unsigned old;
    asm volatile("atom.add.acq_rel.gpu.u32 %0, [%1], %2;" : "=r"(old) : "l"(p), "r"(v) : "memory");
    return old;
}
__device__ __forceinline__ void atom_add_release_gpu(unsigned* p, unsigned v) {
    unsigned old;
    asm volatile("atom.add.release.gpu.u32 %0, [%1], %2;" : "=r"(old) : "l"(p), "r"(v) : "memory");
    (void)old;
}
__device__ __forceinline__ unsigned ld_acquire_gpu(const unsigned* p) {
    unsigned v;
    asm volatile("ld.acquire.gpu.u32 %0, [%1];" : "=r"(v) : "l"(p) : "memory");
    return v;
}
__device__ __forceinline__ void st_relaxed_gpu(unsigned* p, unsigned v) {
    asm volatile("st.relaxed.gpu.u32 [%0], %1;" :: "l"(p), "r"(v) : "memory");
}
__device__ __forceinline__ uint32_t smem_u32(const void* p) {
    uint32_t a;
    asm("{ .reg .u64 t; cvta.to.shared.u64 t, %1; cvt.u32.u64 %0, t; }" : "=r"(a) : "l"(p));
    return a;
}
// 1D bulk G2S copy with mbarrier complete_tx (sm_90 base feature)
__device__ __forceinline__ void bulkcp(uint32_t dst, const void* src, uint32_t bytes,
                                       uint32_t mbar) {
    asm volatile(
        "cp.async.bulk.shared::cluster.global.mbarrier::complete_tx::bytes [%0], [%1], %2, [%3];"
        :: "r"(dst), "l"(src), "r"(bytes), "r"(mbar) : "memory");
}
#define MBARRIER_INIT(mb, c) \
    asm volatile("mbarrier.init.shared.b64 [%0], %1;" :: "r"((uint32_t)(mb)), "r"((uint32_t)(c)) : "memory")
#define MBARRIER_EXPECT_TX(mb, tx) \
    asm volatile("mbarrier.arrive.expect_tx.shared.b64 _, [%0], %1;" \
        :: "r"((uint32_t)(mb)), "r"((uint32_t)(tx)) : "memory")
#define MBARRIER_WAIT_PARITY(mb, par) do {                                            \
    uint32_t _mb = (uint32_t)(mb); uint32_t _p = (uint32_t)(par); uint32_t _done;     \
    asm volatile("{\n\t.reg .pred p;\n\t"                                             \
        "mbarrier.try_wait.parity.acquire.cta.shared::cta.b64 p, [%1], %2;\n\t"       \
        "selp.b32 %0, 1, 0, p;\n\t}" : "=r"(_done) : "r"(_mb), "r"(_p) : "memory");   \
    if (!_done) {                                                                     \
        asm volatile("{\n\t.reg .pred P1;\n\t"                                        \
            "WL_%=:\n\t"                                                              \
            "mbarrier.try_wait.parity.acquire.cta.shared::cta.b64 P1, [%0], %1, 0x989680;\n\t" \
            "@P1 bra.uni WD_%=;\n\t"                                                  \
            "bra.uni WL_%=;\n\t"                                                      \
            "WD_%=:\n\t}" :: "r"(_mb), "r"(_p) : "memory");                           \
    }                                                                                 \
} while (0)

// 16-wide fma2 update (R5-verified)
#define MACBLK(kkv)                                                        \
    {                                                                      \
        ulonglong2 w0v = *(const ulonglong2*)(w0 + (kkv));                 \
        ulonglong2 w1v = *(const ulonglong2*)(w1 + (kkv));                 \
        ulonglong2 av;                                                     \
        av = *(const ulonglong2*)(a0p + (kkv));                            \
        A0  = fma2(w0v.x, av.x, A0);  A1  = fma2(w0v.y, av.y, A1);         \
        A2  = fma2(w1v.x, av.x, A2);  A3  = fma2(w1v.y, av.y, A3);         \
        av = *(const ulonglong2*)(a1p + (kkv));                            \
        A4  = fma2(w0v.x, av.x, A4);  A5  = fma2(w0v.y, av.y, A5);         \
        A6  = fma2(w1v.x, av.x, A6);  A7  = fma2(w1v.y, av.y, A7);         \
        av = *(const ulonglong2*)(a2p + (kkv));                            \
        A8  = fma2(w0v.x, av.x, A8);  A9  = fma2(w0v.y, av.y, A9);         \
        A10 = fma2(w1v.x, av.x, A10); A11 = fma2(w1v.y, av.y, A11);        \
        av = *(const ulonglong2*)(a3p + (kkv));                            \
        A12 = fma2(w0v.x, av.x, A12); A13 = fma2(w0v.y, av.y, A13);        \
        A14 = fma2(w1v.x, av.x, A14); A15 = fma2(w1v.y, av.y, A15);        \
    }

// ============================================================================
// Phase 1: xw[t] = x_t @ Wall^T + (bW + bU)   (R5 code, P1_TT 16 -> 32)
// ============================================================================
#define P1_TT   32
#define P1_WXS  260
#define P1_CKP  132
#define P1_OFF_WX   0
#define P1_OFF_ASH  (P1_OFF_WX + GR * P1_WXS)
#define P1_OFF_GSM  (P1_OFF_ASH + 2 * BATCH * P1_CKP)
#define P1_OFF_BS   (P1_OFF_GSM + 2 * GR * GSTR)
#define P1_FLOATS   (P1_OFF_BS + GR)

__global__ void __launch_bounds__(NTHR, 2)
lstm_xw_kernel(const float* __restrict__ x,
               const float* __restrict__ Wf, const float* __restrict__ bWf,
               const float* __restrict__ Wi, const float* __restrict__ bWi,
               const float* __restrict__ Wo, const float* __restrict__ bWo,
               const float* __restrict__ Wc, const float* __restrict__ bWc,
               const float* __restrict__ bUf, const float* __restrict__ bUi,
               const float* __restrict__ bUo, const float* __restrict__ bUc)
{
    extern __shared__ float sm[];
    float* Wx  = sm + P1_OFF_WX;
    float* ash = sm + P1_OFF_ASH;
    float* gsm = sm + P1_OFF_GSM;
    float* bsm = sm + P1_OFF_BS;

    const int tid = threadIdx.x;
    const int kh  = tid >> 7;
    const int tl  = tid & 127;
    const int cg  = tl & 7;
    const int bg  = tl >> 3;
    const int jg  = blockIdx.x;
    const int j0  = jg * JCOL;
    const int t0  = blockIdx.y * P1_TT;

    {
        const float* Wg[4]  = {Wf, Wi, Wo, Wc};
        const float* bWg[4] = {bWf, bWi, bWo, bWc};
        const float* bUg[4] = {bUf, bUi, bUo, bUc};
        for (int idx = tid; idx < GR * IDIM; idx += NTHR) {
            int row = idx >> 8, k = idx & (IDIM - 1);
            int gate = row >> 2, j = row & 3;
            Wx[row * P1_WXS + k] = Wg[gate][(j0 + j) * IDIM + k];
        }
        if (tid < GR) {
            int gate = tid >> 2, j = tid & 3;
            bsm[tid] = bWg[gate][j0 + j] + bUg[gate][j0 + j];
        }
    }
    __syncthreads();

    const float* w0b = Wx + cg * P1_WXS + kh * 64;
    const float* w1b = Wx + (cg + 8) * P1_WXS + kh * 64;

    for (int tt = 0; tt < P1_TT; ++tt) {
        const int t = t0 + tt;
        const float* xt = x + (size_t)t * BATCH * IDIM;

        #pragma unroll
        for (int r = 0; r < 8; ++r) {
            int idx = tid + r * NTHR;
            int b = idx >> 5, q = idx & 31;
            float4 v = __ldg(reinterpret_cast<const float4*>(xt + b * IDIM + q * 4));
            *reinterpret_cast<float4*>(ash + b * P1_CKP + q * 4) = v;
        }
        __syncthreads();

        ull A0=0,A1=0,A2=0,A3=0,A4=0,A5=0,A6=0,A7=0;
        ull A8=0,A9=0,A10=0,A11=0,A12=0,A13=0,A14=0,A15=0;

        #pragma unroll
        for (int r = 0; r < 8; ++r) {
            int idx = tid + r * NTHR;
            int b = idx >> 5, q = idx & 31;
            float4 v = __ldg(reinterpret_cast<const float4*>(xt + b * IDIM + 128 + q * 4));
            *reinterpret_cast<float4*>(ash + BATCH * P1_CKP + b * P1_CKP + q * 4) = v;
        }
        {
            const float* abase = ash + kh * 64;
            const float* a0p = abase + (bg +  0) * P1_CKP;
            const float* a1p = abase + (bg + 16) * P1_CKP;
            const float* a2p = abase + (bg + 32) * P1_CKP;
            const float* a3p = abase + (bg + 48) * P1_CKP;
            const float* w0 = w0b;
            const float* w1 = w1b;
            #pragma unroll
            for (int kk = 0; kk < 64; kk += 4) MACBLK(kk)
        }
        __syncthreads();
        {
            const float* abase = ash + BATCH * P1_CKP + kh * 64;
            const float* a0p = abase + (bg +  0) * P1_CKP;
            const float* a1p = abase + (bg + 16) * P1_CKP;
            const float* a2p = abase + (bg + 32) * P1_CKP;
            const float* a3p = abase + (bg + 48) * P1_CKP;
            const float* w0 = w0b + 128;
            const float* w1 = w1b + 128;
            #pragma unroll
            for (int kk = 0; kk < 64; kk += 4) MACBLK(kk)
        }
        {
            float* g0 = gsm + kh * GR * GSTR + cg * GSTR + bg;
            float* g1 = gsm + kh * GR * GSTR + (cg + 8) * GSTR + bg;
            g0[ 0] = hsum2(A0)  + hsum2(A1);
            g1[ 0] = hsum2(A2)  + hsum2(A3);
            g0[16] = hsum2(A4)  + hsum2(A5);
            g1[16] = hsum2(A6)  + hsum2(A7);
            g0[32] = hsum2(A8)  + hsum2(A9);
            g1[32] = hsum2(A10) + hsum2(A11);
            g0[48] = hsum2(A12) + hsum2(A13);
            g1[48] = hsum2(A14) + hsum2(A15);
        }
        __syncthreads();
        {
            int row = tid >> 4;
            int b4  = (tid & 15) * 4;
            float4 p0 = *reinterpret_cast<float4*>(gsm + row * GSTR + b4);
            float4 p1 = *reinterpret_cast<float4*>(gsm + GR * GSTR + row * GSTR + b4);
            float bb = bsm[row];
            float4 o;
            o.x = p0.x + p1.x + bb;
            o.y = p0.y + p1.y + bb;
            o.z = p0.z + p1.z + bb;
            o.w = p0.w + p1.w + bb;
            *reinterpret_cast<float4*>(g_xw + (((size_t)t * NCTA + jg) * GR + row) * BATCH + b4) = o;
        }
        __syncthreads();
    }
}

// ============================================================================
// Phase 2: persistent recurrence, bulk-copy staging (no per-thread LSU ops).
// ============================================================================
#define HCHUNK_BYTES (BATCH * HPAD * 4)          // 66560
#define XW_BYTES     (GR * BATCH * 4)            // 4096

// SMEM byte layout
#define RB_MB0   0
#define RB_MB1   8
#define RB_MBX   16
#define RB_EB    24
#define RB_XW    64                               // 2 * 4096
#define RB_GSM   (RB_XW + 2 * XW_BYTES)           // 8256; 4*16*68*4 = 17408
#define RB_WH    (RB_GSM + 4 * GR * GSTR * 4)     // 25664; 16*516*4 = 33024
#define RB_ASH   (RB_WH + GR * 516 * 4)           // 58688 (16B aligned)
#define RB_TOTAL (RB_ASH + 2 * HCHUNK_BYTES)      // 191808

__global__ void __launch_bounds__(NTHR2, 1)
lstm_recur_kernel(const float* __restrict__ Uf, const float* __restrict__ Ui,
                  const float* __restrict__ Uo, const float* __restrict__ Uc,
                  float* __restrict__ out)
{
    extern __shared__ char smem[];
    const uint32_t smu = smem_u32(smem);
    float* xwf = (float*)(smem + RB_XW);
    float* gsm = (float*)(smem + RB_GSM);
    float* Wh  = (float*)(smem + RB_WH);
    float* ash = (float*)(smem + RB_ASH);

    const int tid = threadIdx.x;
    const int kq  = tid >> 7;            // k-quarter 0..3 (64-wide per 256-chunk)
    const int tl  = tid & 127;
    const int cg  = tl & 7;
    const int bg  = tl >> 3;
    const int bx  = blockIdx.x;
    const int j0  = bx * JCOL;

    // prologue
    if (tid == 0) {
        MBARRIER_INIT(smu + RB_MB0, 1);
        MBARRIER_INIT(smu + RB_MB1, 1);
        MBARRIER_INIT(smu + RB_MBX, 1);
        *(unsigned*)(smem + RB_EB) = *(volatile unsigned*)&g_bar_epoch;
    }
    {
        const float* Ug[4] = {Uf, Ui, Uo, Uc};
        for (int idx = tid; idx < GR * HDIM; idx += NTHR2) {
            int row = idx >> 9, k = idx & (HDIM - 1);
            int gate = row >> 2, j = row & 3;
            Wh[row * 516 + k] = Ug[gate][(j0 + j) * HDIM + k];
        }
        // xw(0) into buffer 0 (1024 floats contiguous)
        if (tid < 256) {
            const float* src = g_xw + (size_t)bx * GR * BATCH;
            float4 v = __ldg(reinterpret_cast<const float4*>(src + tid * 4));
            *reinterpret_cast<float4*>(xwf + tid * 4) = v;
        }
    }
    __syncthreads();
    const unsigned base_epoch = *(unsigned*)(smem + RB_EB);

    float* hseq = out;
    float* hfin = out + (size_t)T_STEPS * BATCH * HDIM;
    float* cfin = hfin + BATCH * HDIM;

    const float* w0b = Wh + cg * 516 + kq * 64;
    const float* w1b = Wh + (cg + 8) * 516 + kq * 64;

    // elementwise identity: jj = tid&3, b = tid>>2  (tid < 256)
    const int jj = tid & 3;
    const int eb = tid >> 2;
    float creg = 0.0f;
    // h destination: this CTA's 4 columns live in g_h0 (bx<64) or g_h1
    float* const hcol_base = (bx < 64) ? &g_h0[0][0] : &g_h1[0][0];
    const int hcol_off = (bx < 64) ? j0 : (j0 - 256);

    for (int t = 0; t < T_STEPS; ++t) {
        if (t > 0) {
            if (tid == 0) {
                MBARRIER_EXPECT_TX(smu + RB_MB0, HCHUNK_BYTES);
                bulkcp(smu + RB_ASH, &g_h0[t & 1][0], HCHUNK_BYTES, smu + RB_MB0);
                MBARRIER_EXPECT_TX(smu + RB_MB1, HCHUNK_BYTES);
                bulkcp(smu + RB_ASH + HCHUNK_BYTES, &g_h1[t & 1][0], HCHUNK_BYTES,
                       smu + RB_MB1);
            }

            ull A0=0,A1=0,A2=0,A3=0,A4=0,A5=0,A6=0,A7=0;
            ull A8=0,A9=0,A10=0,A11=0,A12=0,A13=0,A14=0,A15=0;

            MBARRIER_WAIT_PARITY(smu + RB_MB0, (t - 1) & 1);
            {
                const float* abase = ash + kq * 64;
                const float* a0p = abase + (bg +  0) * HPAD;
                const float* a1p = abase + (bg + 16) * HPAD;
                const float* a2p = abase + (bg + 32) * HPAD;
                const float* a3p = abase + (bg + 48) * HPAD;
                const float* w0 = w0b;
                const float* w1 = w1b;
                #pragma unroll
                for (int kk = 0; kk < 64; kk += 4) MACBLK(kk)
            }
            MBARRIER_WAIT_PARITY(smu + RB_MB1, (t - 1) & 1);
            {
                const float* abase = ash + BATCH * HPAD + kq * 64;
                const float* a0p = abase + (bg +  0) * HPAD;
                const float* a1p = abase + (bg + 16) * HPAD;
                const float* a2p = abase + (bg + 32) * HPAD;
                const float* a3p = abase + (bg + 48) * HPAD;
                const float* w0 = w0b + 256;
                const float* w1 = w1b + 256;
                #pragma unroll
                for (int kk = 0; kk < 64; kk += 4) MACBLK(kk)
            }
            {
                float* g0 = gsm + kq * GR * GSTR + cg * GSTR + bg;
                float* g1 = gsm + kq * GR * GSTR + (cg + 8) * GSTR + bg;
                g0[ 0] = hsum2(A0)  + hsum2(A1);
                g1[ 0] = hsum2(A2)  + hsum2(A3);
                g0[16] = hsum2(A4)  + hsum2(A5);
                g1[16] = hsum2(A6)  + hsum2(A7);
                g0[32] = hsum2(A8)  + hsum2(A9);
                g1[32] = hsum2(A10) + hsum2(A11);
                g0[48] = hsum2(A12) + hsum2(A13);
                g1[48] = hsum2(A14) + hsum2(A15);
            }
        }
        __syncthreads();

        // elementwise LSTM update (tid < 256)
        if (tid < 256) {
            if (t > 0) MBARRIER_WAIT_PARITY(smu + RB_MBX, (t - 1) & 1);
            const float* xwb = xwf + (t & 1) * (GR * BATCH);
            float gf = xwb[(0*JCOL+jj)*BATCH + eb];
            float gi = xwb[(1*JCOL+jj)*BATCH + eb];
            float go = xwb[(2*JCOL+jj)*BATCH + eb];
            float gc = xwb[(3*JCOL+jj)*BATCH + eb];
            if (t > 0) {
                #pragma unroll
                for (int q = 0; q < 4; ++q) {
                    gf += gsm[q*GR*GSTR + (0*JCOL+jj)*GSTR + eb];
                    gi += gsm[q*GR*GSTR + (1*JCOL+jj)*GSTR + eb];
                    go += gsm[q*GR*GSTR + (2*JCOL+jj)*GSTR + eb];
                    gc += gsm[q*GR*GSTR + (3*JCOL+jj)*GSTR + eb];
                }
            }
            float fg = sigmoidf_(gf);
            float ig = sigmoidf_(gi);
            float og = sigmoidf_(go);
            float cc = tanhf(gc);
            float cnew = fg * creg + ig * cc;
            creg = cnew;
            float h = og * tanhf(cnew);
            __stcg(hcol_base + (size_t)((t + 1) & 1) * BATCH * HPAD
                             + eb * HPAD + hcol_off + jj, h);
            __stcs(hseq + ((size_t)t * BATCH + eb) * HDIM + j0 + jj, h);
            if (t == T_STEPS - 1) {
                hfin[eb * HDIM + j0 + jj] = h;
                cfin[eb * HDIM + j0 + jj] = cnew;
            }
        }

        if (t < T_STEPS - 1) {
            // prefetch next xw block (independent of h) into other buffer
            if (tid == 0) {
                MBARRIER_EXPECT_TX(smu + RB_MBX, XW_BYTES);
                bulkcp(smu + RB_XW + ((t + 1) & 1) * XW_BYTES,
                       g_xw + ((size_t)(t + 1) * NCTA + bx) * GR * BATCH,
                       XW_BYTES, smu + RB_MBX);
            }
            __syncthreads();
            if (tid == 0) {
                unsigned old = atom_add_acqrel_gpu(&g_bar_count, 1u);
                if (old == NCTA - 1) {
                    st_relaxed_gpu(&g_bar_count, 0u);
                    atom_add_release_gpu(&g_bar_epoch, 1u);
                } else {
                    unsigned target = base_epoch + (unsigned)(t + 1);
                    while ((int)(ld_acquire_gpu(&g_bar_epoch) - target) < 0) { }
                }
            }
            __syncthreads();
        }
    }
}

extern "C" void kernel_launch(void* const* d_in, const int* in_sizes, int n_in,
                              void* d_out, int out_size)
{
    (void)in_sizes; (void)n_in; (void)out_size;
    const float* x   = (const float*)d_in[0];
    const float* Wf  = (const float*)d_in[1];
    const float* bWf = (const float*)d_in[2];
    const float* Wi  = (const float*)d_in[3];
    const float* bWi = (const float*)d_in[4];
    const float* Wo  = (const float*)d_in[5];
    const float* bWo = (const float*)d_in[6];
    const float* Wc  = (const float*)d_in[7];
    const float* bWc = (const float*)d_in[8];
    const float* Uf  = (const float*)d_in[9];
    const float* bUf = (const float*)d_in[10];
    const float* Ui  = (const float*)d_in[11];
    const float* bUi = (const float*)d_in[12];
    const float* Uo  = (const float*)d_in[13];
    const float* bUo = (const float*)d_in[14];
    const float* Uc  = (const float*)d_in[15];
    const float* bUc = (const float*)d_in[16];

    size_t p1_smem = P1_FLOATS * sizeof(float);
    cudaFuncSetAttribute(lstm_xw_kernel,
                         cudaFuncAttributeMaxDynamicSharedMemorySize, (int)p1_smem);
    cudaFuncSetAttribute(lstm_recur_kernel,
                         cudaFuncAttributeMaxDynamicSharedMemorySize, RB_TOTAL);

    dim3 g1(NCTA, T_STEPS / P1_TT);
    lstm_xw_kernel<<<g1, NTHR, p1_smem>>>(
        x, Wf, bWf, Wi, bWi, Wo, bWo, Wc, bWc, bUf, bUi, bUo, bUc);

    lstm_recur_kernel<<<NCTA, NTHR2, RB_TOTAL>>>(Uf, Ui, Uo, Uc, (float*)d_out);
}

// round 9
// speedup vs baseline: 1.5149x; 1.2479x over previous
#include <cuda_runtime.h>
#include <cuda_bf16.h>
#include <cstdint>

#define T_STEPS 512
#define BATCH   64
#define IDIM    256
#define HDIM    512
#define NCTA    128
#define NTHR    256
#define NTHR2   512
#define JCOL    4
#define GR      16
#define GSTR    68
#define HROWP   264            // bf16 per padded A row (528 B; 528 mod 128 = 16)
#define USTR    520            // bf16 per padded U row (1040 B; mod 128 = 16)

typedef unsigned long long ull;

// ---- persistent device scratch ----
__device__ float g_xw[(size_t)T_STEPS * NCTA * GR * BATCH];     // [t][jg][row16][b]
// A chunks: [buf][khalf][row(128: 0-63 hi, 64-127 lo) * HROWP]
__device__ __nv_bfloat16 g_ha[2][2][128 * HROWP];
__device__ unsigned int g_bar_count;
__device__ unsigned int g_bar_epoch;

// ---------------- helpers ----------------
__device__ __forceinline__ ull fma2(ull a, ull b, ull c) {
    ull d;
    asm("fma.rn.f32x2 %0, %1, %2, %3;" : "=l"(d) : "l"(a), "l"(b), "l"(c));
    return d;
}
__device__ __forceinline__ float hsum2(ull a) {
    return __uint_as_float((unsigned)(a & 0xffffffffu)) +
           __uint_as_float((unsigned)(a >> 32));
}
__device__ __forceinline__ float sigmoidf_(float v) {
    return __fdividef(1.0f, 1.0f + __expf(-v));
}
__device__ __forceinline__ unsigned atom_add_acqrel_gpu(unsigned* p, unsigned v) {
    unsigned old;
    asm volatile("atom.add.acq_rel.gpu.u32 %0, [%1], %2;" : "=r"(old) : "l"(p), "r"(v) : "memory");
    return old;
}
__device__ __forceinline__ void atom_add_release_gpu(unsigned* p, unsigned v) {
    unsigned old;
    asm volatile("atom.add.release.gpu.u32 %0, [%1], %2;" : "=r"(old) : "l"(p), "r"(v) : "memory");
    (void)old;
}
__device__ __forceinline__ unsigned ld_acquire_gpu(const unsigned* p) {
    unsigned v;
    asm volatile("ld.acquire.gpu.u32 %0, [%1];" : "=r"(v) : "l"(p) : "memory");
    return v;
}
__device__ __forceinline__ void st_relaxed_gpu(unsigned* p, unsigned v) {
    asm volatile("st.relaxed.gpu.u32 [%0], %1;" :: "l"(p), "r"(v) : "memory");
}
__device__ __forceinline__ uint32_t smem_u32(const void* p) {
    uint32_t a;
    asm("{ .reg .u64 t; cvta.to.shared.u64 t, %1; cvt.u32.u64 %0, t; }" : "=r"(a) : "l"(p));
    return a;
}
__device__ __forceinline__ void bulkcp(uint32_t dst, const void* src, uint32_t bytes,
                                       uint32_t mbar) {
    asm volatile(
        "cp.async.bulk.shared::cluster.global.mbarrier::complete_tx::bytes [%0], [%1], %2, [%3];"
        :: "r"(dst), "l"(src), "r"(bytes), "r"(mbar) : "memory");
}
#define MBARRIER_INIT(mb, c) \
    asm volatile("mbarrier.init.shared.b64 [%0], %1;" :: "r"((uint32_t)(mb)), "r"((uint32_t)(c)) : "memory")
#define MBARRIER_EXPECT_TX(mb, tx) \
    asm volatile("mbarrier.arrive.expect_tx.shared.b64 _, [%0], %1;" \
        :: "r"((uint32_t)(mb)), "r"((uint32_t)(tx)) : "memory")
#define MBARRIER_WAIT_PARITY(mb, par) do {                                            \
    uint32_t _mb = (uint32_t)(mb); uint32_t _p = (uint32_t)(par); uint32_t _done;     \
    asm volatile("{\n\t.reg .pred p;\n\t"                                             \
        "mbarrier.try_wait.parity.acquire.cta.shared::cta.b64 p, [%1], %2;\n\t"       \
        "selp.b32 %0, 1, 0, p;\n\t}" : "=r"(_done) : "r"(_mb), "r"(_p) : "memory");   \
    if (!_done) {                                                                     \
        asm volatile("{\n\t.reg .pred P1;\n\t"                                        \
            "WL_%=:\n\t"                                                              \
            "mbarrier.try_wait.parity.acquire.cta.shared::cta.b64 P1, [%0], %1, 0x989680;\n\t" \
            "@P1 bra.uni WD_%=;\n\t"                                                  \
            "bra.uni WL_%=;\n\t"                                                      \
            "WD_%=:\n\t}" :: "r"(_mb), "r"(_p) : "memory");                           \
    }                                                                                 \
} while (0)

// 16-wide fma2 update (phase-1 only, R5-verified)
#define MACBLK(kkv)                                                        \
    {                                                                      \
        ulonglong2 w0v = *(const ulonglong2*)(w0 + (kkv));                 \
        ulonglong2 w1v = *(const ulonglong2*)(w1 + (kkv));                 \
        ulonglong2 av;                                                     \
        av = *(const ulonglong2*)(a0p + (kkv));                            \
        A0  = fma2(w0v.x, av.x, A0);  A1  = fma2(w0v.y, av.y, A1);         \
        A2  = fma2(w1v.x, av.x, A2);  A3  = fma2(w1v.y, av.y, A3);         \
        av = *(const ulonglong2*)(a1p + (kkv));                            \
        A4  = fma2(w0v.x, av.x, A4);  A5  = fma2(w0v.y, av.y, A5);         \
        A6  = fma2(w1v.x, av.x, A6);  A7  = fma2(w1v.y, av.y, A7);         \
        av = *(const ulonglong2*)(a2p + (kkv));                            \
        A8  = fma2(w0v.x, av.x, A8);  A9  = fma2(w0v.y, av.y, A9);         \
        A10 = fma2(w1v.x, av.x, A10); A11 = fma2(w1v.y, av.y, A11);        \
        av = *(const ulonglong2*)(a3p + (kkv));                            \
        A12 = fma2(w0v.x, av.x, A12); A13 = fma2(w0v.y, av.y, A13);        \
        A14 = fma2(w1v.x, av.x, A14); A15 = fma2(w1v.y, av.y, A15);        \
    }

// ============================================================================
// Phase 1 (unchanged, R8-verified): xw[t] = x_t @ Wall^T + (bW + bU)
// ============================================================================
#define P1_TT   32
#define P1_WXS  260
#define P1_CKP  132
#define P1_OFF_WX   0
#define P1_OFF_ASH  (P1_OFF_WX + GR * P1_WXS)
#define P1_OFF_GSM  (P1_OFF_ASH + 2 * BATCH * P1_CKP)
#define P1_OFF_BS   (P1_OFF_GSM + 2 * GR * GSTR)
#define P1_FLOATS   (P1_OFF_BS + GR)

__global__ void __launch_bounds__(NTHR, 2)
lstm_xw_kernel(const float* __restrict__ x,
               const float* __restrict__ Wf, const float* __restrict__ bWf,
               const float* __restrict__ Wi, const float* __restrict__ bWi,
               const float* __restrict__ Wo, const float* __restrict__ bWo,
               const float* __restrict__ Wc, const float* __restrict__ bWc,
               const float* __restrict__ bUf, const float* __restrict__ bUi,
               const float* __restrict__ bUo, const float* __restrict__ bUc)
{
    extern __shared__ float sm[];
    float* Wx  = sm + P1_OFF_WX;
    float* ash = sm + P1_OFF_ASH;
    float* gsm = sm + P1_OFF_GSM;
    float* bsm = sm + P1_OFF_BS;

    const int tid = threadIdx.x;
    const int kh  = tid >> 7;
    const int tl  = tid & 127;
    const int cg  = tl & 7;
    const int bg  = tl >> 3;
    const int jg  = blockIdx.x;
    const int j0  = jg * JCOL;
    const int t0  = blockIdx.y * P1_TT;

    {
        const float* Wg[4]  = {Wf, Wi, Wo, Wc};
        const float* bWg[4] = {bWf, bWi, bWo, bWc};
        const float* bUg[4] = {bUf, bUi, bUo, bUc};
        for (int idx = tid; idx < GR * IDIM; idx += NTHR) {
            int row = idx >> 8, k = idx & (IDIM - 1);
            int gate = row >> 2, j = row & 3;
            Wx[row * P1_WXS + k] = Wg[gate][(j0 + j) * IDIM + k];
        }
        if (tid < GR) {
            int gate = tid >> 2, j = tid & 3;
            bsm[tid] = bWg[gate][j0 + j] + bUg[gate][j0 + j];
        }
    }
    __syncthreads();

    const float* w0b = Wx + cg * P1_WXS + kh * 64;
    const float* w1b = Wx + (cg + 8) * P1_WXS + kh * 64;

    for (int tt = 0; tt < P1_TT; ++tt) {
        const int t = t0 + tt;
        const float* xt = x + (size_t)t * BATCH * IDIM;

        #pragma unroll
        for (int r = 0; r < 8; ++r) {
            int idx = tid + r * NTHR;
            int b = idx >> 5, q = idx & 31;
            float4 v = __ldg(reinterpret_cast<const float4*>(xt + b * IDIM + q * 4));
            *reinterpret_cast<float4*>(ash + b * P1_CKP + q * 4) = v;
        }
        __syncthreads();

        ull A0=0,A1=0,A2=0,A3=0,A4=0,A5=0,A6=0,A7=0;
        ull A8=0,A9=0,A10=0,A11=0,A12=0,A13=0,A14=0,A15=0;

        #pragma unroll
        for (int r = 0; r < 8; ++r) {
            int idx = tid + r * NTHR;
            int b = idx >> 5, q = idx & 31;
            float4 v = __ldg(reinterpret_cast<const float4*>(xt + b * IDIM + 128 + q * 4));
            *reinterpret_cast<float4*>(ash + BATCH * P1_CKP + b * P1_CKP + q * 4) = v;
        }
        {
            const float* abase = ash + kh * 64;
            const float* a0p = abase + (bg +  0) * P1_CKP;
            const float* a1p = abase + (bg + 16) * P1_CKP;
            const float* a2p = abase + (bg + 32) * P1_CKP;
            const float* a3p = abase + (bg + 48) * P1_CKP;
            const float* w0 = w0b;
            const float* w1 = w1b;
            #pragma unroll
            for (int kk = 0; kk < 64; kk += 4) MACBLK(kk)
        }
        __syncthreads();
        {
            const float* abase = ash + BATCH * P1_CKP + kh * 64;
            const float* a0p = abase + (bg +  0) * P1_CKP;
            const float* a1p = abase + (bg + 16) * P1_CKP;
            const float* a2p = abase + (bg + 32) * P1_CKP;
            const float* a3p = abase + (bg + 48) * P1_CKP;
            const float* w0 = w0b + 128;
            const float* w1 = w1b + 128;
            #pragma unroll
            for (int kk = 0; kk < 64; kk += 4) MACBLK(kk)
        }
        {
            float* g0 = gsm + kh * GR * GSTR + cg * GSTR + bg;
            float* g1 = gsm + kh * GR * GSTR + (cg + 8) * GSTR + bg;
            g0[ 0] = hsum2(A0)  + hsum2(A1);
            g1[ 0] = hsum2(A2)  + hsum2(A3);
            g0[16] = hsum2(A4)  + hsum2(A5);
            g1[16] = hsum2(A6)  + hsum2(A7);
            g0[32] = hsum2(A8)  + hsum2(A9);
            g1[32] = hsum2(A10) + hsum2(A11);
            g0[48] = hsum2(A12) + hsum2(A13);
            g1[48] = hsum2(A14) + hsum2(A15);
        }
        __syncthreads();
        {
            int row = tid >> 4;
            int b4  = (tid & 15) * 4;
            float4 p0 = *reinterpret_cast<float4*>(gsm + row * GSTR + b4);
            float4 p1 = *reinterpret_cast<float4*>(gsm + GR * GSTR + row * GSTR + b4);
            float bb = bsm[row];
            float4 o;
            o.x = p0.x + p1.x + bb;
            o.y = p0.y + p1.y + bb;
            o.z = p0.z + p1.z + bb;
            o.w = p0.w + p1.w + bb;
            *reinterpret_cast<float4*>(g_xw + (((size_t)t * NCTA + jg) * GR + row) * BATCH + b4) = o;
        }
        __syncthreads();
    }
}

// ============================================================================
// Phase 2: persistent recurrence with mma.sync (bf16 hi/lo split).
// ============================================================================
#define ACHUNK_BYTES (128 * HROWP * 2)        // 67584
#define XW_BYTES     (GR * BATCH * 4)         // 4096

#define RB_MB0   0
#define RB_MB1   8
#define RB_MBX   16
#define RB_EB    24
#define RB_XW    64
#define RB_GSM   (RB_XW + 2 * XW_BYTES)       // 8256 bytes in; gsm 128*20*4 = 10240
#define RB_U     (RB_GSM + 10240)             // hi 16*1040 + lo 16*1040 = 33280
#define RB_A     (RB_U + 33280)               // 2 * 67584 = 135168
#define RB_TOTAL (RB_A + 2 * ACHUNK_BYTES)    // 186944

__global__ void __launch_bounds__(NTHR2, 1)
lstm_recur_kernel(const float* __restrict__ Uf, const float* __restrict__ Ui,
                  const float* __restrict__ Uo, const float* __restrict__ Uc,
                  float* __restrict__ out)
{
    extern __shared__ char smem[];
    const uint32_t smu = smem_u32(smem);
    float* xwf = (float*)(smem + RB_XW);
    float* gsm = (float*)(smem + RB_GSM);

    const int tid  = threadIdx.x;
    const int wid  = tid >> 5;
    const int lane = tid & 31;
    const int bx   = blockIdx.x;
    const int j0   = bx * JCOL;
    const int mt   = wid & 7;          // m-tile 0..7 (rows mt*16..+16)
    const int nt   = wid >> 3;         // n-tile 0..1 (cols nt*8..+8)

    if (tid == 0) {
        MBARRIER_INIT(smu + RB_MB0, 1);
        MBARRIER_INIT(smu + RB_MB1, 1);
        MBARRIER_INIT(smu + RB_MBX, 1);
        *(unsigned*)(smem + RB_EB) = *(volatile unsigned*)&g_bar_epoch;
    }
    // U -> split bf16 padded SMEM (hi @ RB_U, lo @ RB_U + 16*1040)
    {
        const float* Ug[4] = {Uf, Ui, Uo, Uc};
        for (int i = 0; i < 16; ++i) {
            int idx = tid + i * NTHR2;       // 0..8191
            int row = idx >> 9;              // 0..15 (gate*4 + j)
            int k   = idx & 511;
            float f = Ug[row >> 2][(j0 + (row & 3)) * HDIM + k];
            __nv_bfloat16 hi = __float2bfloat16_rn(f);
            __nv_bfloat16 lo = __float2bfloat16_rn(f - __bfloat162float(hi));
            *(__nv_bfloat16*)(smem + RB_U + (row * USTR + k) * 2) = hi;
            *(__nv_bfloat16*)(smem + RB_U + 16 * USTR * 2 + (row * USTR + k) * 2) = lo;
        }
        if (tid < 256) {
            const float* src = g_xw + (size_t)bx * GR * BATCH;
            float4 v = __ldg(reinterpret_cast<const float4*>(src + tid * 4));
            *reinterpret_cast<float4*>(xwf + tid * 4) = v;
        }
    }
    __syncthreads();
    const unsigned base_epoch = *(unsigned*)(smem + RB_EB);

    float* hseq = out;
    float* hfin = out + (size_t)T_STEPS * BATCH * HDIM;
    float* cfin = hfin + BATCH * HDIM;

    // fragment lane address offsets
    const uint32_t a_lane = (uint32_t)(lane & 15) * (HROWP * 2) + (uint32_t)((lane >> 4) << 4);
    const uint32_t b_lane = (uint32_t)(lane & 7) * (USTR * 2) + (uint32_t)(((lane >> 3) & 1) << 4);
    const uint32_t abase0 = smu + RB_A + (uint32_t)mt * 16 * (HROWP * 2) + a_lane;
    const uint32_t bhib   = smu + RB_U + (uint32_t)nt * 8 * (USTR * 2) + b_lane;
    const uint32_t blob   = bhib + 16 * USTR * 2;

    // elementwise identity
    const int jj = tid & 3;
    const int eb = tid >> 2;
    float creg = 0.0f;
    const int hchunk = j0 >> 8;                 // this CTA's 4 cols share one K-half
    const int hcc    = (j0 & 255) + 0;          // + jj at use

    for (int t = 0; t < T_STEPS; ++t) {
        if (t > 0) {
            if (tid == 0) {
                MBARRIER_EXPECT_TX(smu + RB_MB0, ACHUNK_BYTES);
                bulkcp(smu + RB_A, &g_ha[t & 1][0][0], ACHUNK_BYTES, smu + RB_MB0);
                MBARRIER_EXPECT_TX(smu + RB_MB1, ACHUNK_BYTES);
                bulkcp(smu + RB_A + ACHUNK_BYTES, &g_ha[t & 1][1][0], ACHUNK_BYTES,
                       smu + RB_MB1);
            }

            float d0 = 0.f, d1 = 0.f, d2 = 0.f, d3 = 0.f;

            #pragma unroll
            for (int c = 0; c < 2; ++c) {
                if (c == 0) { MBARRIER_WAIT_PARITY(smu + RB_MB0, (t - 1) & 1); }
                else        { MBARRIER_WAIT_PARITY(smu + RB_MB1, (t - 1) & 1); }
                const uint32_t ab = abase0 + (uint32_t)c * ACHUNK_BYTES;
                const uint32_t bofs = (uint32_t)c * 512;   // k-byte offset within U row
                #pragma unroll
                for (int k = 0; k < 16; ++k) {
                    uint32_t a0, a1, a2, a3, b0, b1;
                    asm volatile(
                        "ldmatrix.sync.aligned.m8n8.x4.shared.b16 {%0,%1,%2,%3}, [%4];"
                        : "=r"(a0), "=r"(a1), "=r"(a2), "=r"(a3)
                        : "r"(ab + (uint32_t)k * 32));
                    asm volatile(
                        "ldmatrix.sync.aligned.m8n8.x2.shared.b16 {%0,%1}, [%2];"
                        : "=r"(b0), "=r"(b1) : "r"(bhib + bofs + (uint32_t)k * 32));
                    asm volatile(
                        "mma.sync.aligned.m16n8k16.row.col.f32.bf16.bf16.f32 "
                        "{%0,%1,%2,%3}, {%4,%5,%6,%7}, {%8,%9}, {%0,%1,%2,%3};"
                        : "+f"(d0), "+f"(d1), "+f"(d2), "+f"(d3)
                        : "r"(a0), "r"(a1), "r"(a2), "r"(a3), "r"(b0), "r"(b1));
                    asm volatile(
                        "ldmatrix.sync.aligned.m8n8.x2.shared.b16 {%0,%1}, [%2];"
                        : "=r"(b0), "=r"(b1) : "r"(blob + bofs + (uint32_t)k * 32));
                    asm volatile(
                        "mma.sync.aligned.m16n8k16.row.col.f32.bf16.bf16.f32 "
                        "{%0,%1,%2,%3}, {%4,%5,%6,%7}, {%8,%9}, {%0,%1,%2,%3};"
                        : "+f"(d0), "+f"(d1), "+f"(d2), "+f"(d3)
                        : "r"(a0), "r"(a1), "r"(a2), "r"(a3), "r"(b0), "r"(b1));
                }
            }
            // store D frags: thread holds rows m, m+8; cols n, n+1
            {
                int m = mt * 16 + (lane >> 2);
                int n = nt * 8 + 2 * (lane & 3);
                gsm[m * 20 + n]           = d0;
                gsm[m * 20 + n + 1]       = d1;
                gsm[(m + 8) * 20 + n]     = d2;
                gsm[(m + 8) * 20 + n + 1] = d3;
            }
        }
        __syncthreads();

        // elementwise LSTM update (tid < 256)
        if (tid < 256) {
            if (t > 0) MBARRIER_WAIT_PARITY(smu + RB_MBX, (t - 1) & 1);
            const float* xwb = xwf + (t & 1) * (GR * BATCH);
            float gv[4];
            #pragma unroll
            for (int g = 0; g < 4; ++g) {
                float v = xwb[(g * JCOL + jj) * BATCH + eb];
                if (t > 0) {
                    int n = g * 4 + jj;
                    v += gsm[eb * 20 + n] + gsm[(eb + 64) * 20 + n];
                }
                gv[g] = v;
            }
            float fg = sigmoidf_(gv[0]);
            float ig = sigmoidf_(gv[1]);
            float og = sigmoidf_(gv[2]);
            float cc = tanhf(gv[3]);
            float cnew = fg * creg + ig * cc;
            creg = cnew;
            float h = og * tanhf(cnew);
            __nv_bfloat16 hi = __float2bfloat16_rn(h);
            __nv_bfloat16 lo = __float2bfloat16_rn(h - __bfloat162float(hi));
            int nb = (t + 1) & 1;
            g_ha[nb][hchunk][eb * HROWP + hcc + jj]        = hi;
            g_ha[nb][hchunk][(eb + 64) * HROWP + hcc + jj] = lo;
            __stcs(hseq + ((size_t)t * BATCH + eb) * HDIM + j0 + jj, h);
            if (t == T_STEPS - 1) {
                hfin[eb * HDIM + j0 + jj] = h;
                cfin[eb * HDIM + j0 + jj] = cnew;
            }
        }

        if (t < T_STEPS - 1) {
            if (tid == 0) {
                MBARRIER_EXPECT_TX(smu + RB_MBX, XW_BYTES);
                bulkcp(smu + RB_XW + ((t + 1) & 1) * XW_BYTES,
                       g_xw + ((size_t)(t + 1) * NCTA + bx) * GR * BATCH,
                       XW_BYTES, smu + RB_MBX);
            }
            __syncthreads();
            if (tid == 0) {
                unsigned old = atom_add_acqrel_gpu(&g_bar_count, 1u);
                if (old == NCTA - 1) {
                    st_relaxed_gpu(&g_bar_count, 0u);
                    atom_add_release_gpu(&g_bar_epoch, 1u);
                } else {
                    unsigned target = base_epoch + (unsigned)(t + 1);
                    while ((int)(ld_acquire_gpu(&g_bar_epoch) - target) < 0) { }
                }
            }
            __syncthreads();
        }
    }
}

extern "C" void kernel_launch(void* const* d_in, const int* in_sizes, int n_in,
                              void* d_out, int out_size)
{
    (void)in_sizes; (void)n_in; (void)out_size;
    const float* x   = (const float*)d_in[0];
    const float* Wf  = (const float*)d_in[1];
    const float* bWf = (const float*)d_in[2];
    const float* Wi  = (const float*)d_in[3];
    const float* bWi = (const float*)d_in[4];
    const float* Wo  = (const float*)d_in[5];
    const float* bWo = (const float*)d_in[6];
    const float* Wc  = (const float*)d_in[7];
    const float* bWc = (const float*)d_in[8];
    const float* Uf  = (const float*)d_in[9];
    const float* bUf = (const float*)d_in[10];
    const float* Ui  = (const float*)d_in[11];
    const float* bUi = (const float*)d_in[12];
    const float* Uo  = (const float*)d_in[13];
    const float* bUo = (const float*)d_in[14];
    const float* Uc  = (const float*)d_in[15];
    const float* bUc = (const float*)d_in[16];

    size_t p1_smem = P1_FLOATS * sizeof(float);
    cudaFuncSetAttribute(lstm_xw_kernel,
                         cudaFuncAttributeMaxDynamicSharedMemorySize, (int)p1_smem);
    cudaFuncSetAttribute(lstm_recur_kernel,
                         cudaFuncAttributeMaxDynamicSharedMemorySize, RB_TOTAL);

    dim3 g1(NCTA, T_STEPS / P1_TT);
    lstm_xw_kernel<<<g1, NTHR, p1_smem>>>(
        x, Wf, bWf, Wi, bWi, Wo, bWo, Wc, bWc, bUf, bUi, bUo, bUc);

    lstm_recur_kernel<<<NCTA, NTHR2, RB_TOTAL>>>(Uf, Ui, Uo, Uc, (float*)d_out);
}